// round 9
// baseline (speedup 1.0000x reference)
#include <cuda_runtime.h>
#include <math.h>
#include <stdint.h>
#include <stddef.h>

#define NN 50000
#define EE 800000

// ---------------- scratch (static __device__, no allocation) ----------------
static __device__ int   g_src[EE];       // edge order
static __device__ int   g_dst[EE];       // edge order
static __device__ int   g_pos[EE];       // edge id -> CSR slot
static __device__ int   g_srcc[EE];      // CSR order
static __device__ int   g_dstc[EE];      // CSR order
static __device__ int   g_deg[NN];
static __device__ int   g_off[NN + 1];
static __device__ int   g_cur[NN];
static __device__ float g_efA[(size_t)EE * 64];   // CSR order
static __device__ float g_efB[(size_t)EE * 64];   // CSR order
static __device__ float g_xsp[(size_t)NN * 64];
static __device__ float g_xdp[(size_t)NN * 64];
static __device__ float g_xv [(size_t)NN * 128];
static __device__ float g_ss [NN * 8];
static __device__ float g_sd [NN * 8];
static __device__ float g_h1 [(size_t)NN * 256];
static __device__ float g_h2 [(size_t)NN * 256];
static __device__ float g_xg [(size_t)NN * 320];
static __device__ float g_wae[64 * 8];

__device__ __forceinline__ float elu1(float x) { return x > 0.f ? x : expm1f(x); }
__device__ __forceinline__ float lrelu(float x) { return x > 0.f ? x : 0.2f * x; }

// ---------------- prep: dtype detect (per-block, deterministic) + conv + zero ----
__global__ void prep_kernel(const int* __restrict__ a32) {
    int tid = threadIdx.x;
    int nz = (tid < 256 && a32[2 * tid + 1] != 0) ? 1 : 0;
    int is64 = (__syncthreads_or(nz) == 0);
    int i = blockIdx.x * blockDim.x + tid;
    if (i < EE) {
        if (is64) {
            g_src[i] = a32[2 * (size_t)i];
            g_dst[i] = a32[2 * (size_t)EE + 2 * (size_t)i];
        } else {
            g_src[i] = a32[i];
            g_dst[i] = a32[(size_t)EE + i];
        }
    }
    if (i < NN) g_deg[i] = 0;
}

// ---------------- CSR build ----------------
__global__ void count_kernel() {
    int i = blockIdx.x * blockDim.x + threadIdx.x;
    if (i < EE) atomicAdd(&g_deg[g_dst[i]], 1);
}

// single-block warp-shfl scan: 4 barriers per 1024-chunk (was 20)
__global__ void scan_kernel() {
    __shared__ int wsum[32];
    __shared__ int carry_s;
    int tid = threadIdx.x;
    int lane = tid & 31, wid = tid >> 5;
    if (tid == 0) carry_s = 0;
    __syncthreads();
    for (int base = 0; base < NN; base += 1024) {
        int i = base + tid;
        int v = (i < NN) ? g_deg[i] : 0;
        int x = v;
#pragma unroll
        for (int d = 1; d < 32; d <<= 1) {
            int t = __shfl_up_sync(0xffffffffu, x, d);
            if (lane >= d) x += t;
        }
        if (lane == 31) wsum[wid] = x;
        __syncthreads();
        if (wid == 0) {
            int w = wsum[lane];
            int y = w;
#pragma unroll
            for (int d = 1; d < 32; d <<= 1) {
                int t = __shfl_up_sync(0xffffffffu, y, d);
                if (lane >= d) y += t;
            }
            wsum[lane] = y - w;   // exclusive warp offsets
        }
        __syncthreads();
        int carry = carry_s;
        int ex = carry + wsum[wid] + x - v;
        if (i < NN) { g_off[i] = ex; g_cur[i] = ex; }
        __syncthreads();
        if (tid == 1023) carry_s = carry + wsum[31] + x;  // + block total
        __syncthreads();
    }
    if (tid == 0) g_off[NN] = carry_s;
}

__global__ void scatter_kernel() {
    int i = blockIdx.x * blockDim.x + threadIdx.x;
    if (i < EE) {
        int d = g_dst[i];
        int p = atomicAdd(&g_cur[d], 1);
        g_pos[i]  = p;
        g_srcc[p] = g_src[i];
        g_dstc[p] = d;
    }
}

// ---------------- GEMM core: 128x64 tile, 4x8 microtile, 256 threads ----------
template <int MODE>
__device__ __forceinline__ void gemm_body(
        const float* __restrict__ A, const float* __restrict__ W,
        float* __restrict__ C, int M, int K, int Wld, int cof, int Cld,
        const float* __restrict__ bias, int bm) {
    __shared__ float As[16][132];
    __shared__ float Bs[16][68];
    int tid = threadIdx.x;
    int wid = tid >> 5, lane = tid & 31;
    int wm = (wid & 3) * 32, wn = (wid >> 2) * 32;
    int m_off = wm + (lane & 7) * 4;
    int n_off = wn + (lane >> 3) * 8;

    float acc[4][8];
#pragma unroll
    for (int i = 0; i < 4; i++)
#pragma unroll
        for (int j = 0; j < 8; j++) acc[i][j] = 0.f;

    for (int k0 = 0; k0 < K; k0 += 16) {
#pragma unroll
        for (int t = tid; t < 512; t += 256) {
            int row = t >> 2, seg = t & 3;
            float4 av = make_float4(0.f, 0.f, 0.f, 0.f);
            if (bm + row < M) av = *(const float4*)&A[(size_t)(bm + row) * K + k0 + seg * 4];
            As[seg * 4 + 0][row] = av.x;
            As[seg * 4 + 1][row] = av.y;
            As[seg * 4 + 2][row] = av.z;
            As[seg * 4 + 3][row] = av.w;
        }
        {
            int kk = tid >> 4, ns = tid & 15;
            float4 wv = *(const float4*)&W[(size_t)(k0 + kk) * Wld + cof + ns * 4];
            *(float4*)&Bs[kk][ns * 4] = wv;
        }
        __syncthreads();
#pragma unroll
        for (int k = 0; k < 16; ++k) {
            float4 a  = *(const float4*)&As[k][m_off];
            float4 b0 = *(const float4*)&Bs[k][n_off];
            float4 b1 = *(const float4*)&Bs[k][n_off + 4];
            float am[4] = {a.x, a.y, a.z, a.w};
            float bv[8] = {b0.x, b0.y, b0.z, b0.w, b1.x, b1.y, b1.z, b1.w};
#pragma unroll
            for (int i = 0; i < 4; i++)
#pragma unroll
                for (int j = 0; j < 8; j++)
                    acc[i][j] = fmaf(am[i], bv[j], acc[i][j]);
        }
        __syncthreads();
    }

    if (MODE == 0) {
#pragma unroll
        for (int i = 0; i < 4; i++) {
            int r = bm + m_off + i;
            if (r < M) {
                float4 v0 = make_float4(acc[i][0], acc[i][1], acc[i][2], acc[i][3]);
                float4 v1 = make_float4(acc[i][4], acc[i][5], acc[i][6], acc[i][7]);
                *(float4*)&C[(size_t)r * Cld + cof + n_off]     = v0;
                *(float4*)&C[(size_t)r * Cld + cof + n_off + 4] = v1;
            }
        }
    } else {
        float4 bv0 = *(const float4*)&bias[n_off];
        float4 bv1 = *(const float4*)&bias[n_off + 4];
#pragma unroll
        for (int i = 0; i < 4; i++) {
            int r = bm + m_off + i;
            if (r < M) {
                int s, d, ro;
                if (MODE == 1) { s = g_src[r];  d = g_dst[r];  ro = g_pos[r]; }
                else           { s = g_srcc[r]; d = g_dstc[r]; ro = r; }
                float4 a0 = *(const float4*)&g_xsp[(size_t)s * 64 + n_off];
                float4 a1 = *(const float4*)&g_xsp[(size_t)s * 64 + n_off + 4];
                float4 b0 = *(const float4*)&g_xdp[(size_t)d * 64 + n_off];
                float4 b1 = *(const float4*)&g_xdp[(size_t)d * 64 + n_off + 4];
                float4 v0, v1;
                v0.x = fmaxf(acc[i][0] + a0.x + b0.x + bv0.x, 0.f);
                v0.y = fmaxf(acc[i][1] + a0.y + b0.y + bv0.y, 0.f);
                v0.z = fmaxf(acc[i][2] + a0.z + b0.z + bv0.z, 0.f);
                v0.w = fmaxf(acc[i][3] + a0.w + b0.w + bv0.w, 0.f);
                v1.x = fmaxf(acc[i][4] + a1.x + b1.x + bv1.x, 0.f);
                v1.y = fmaxf(acc[i][5] + a1.y + b1.y + bv1.y, 0.f);
                v1.z = fmaxf(acc[i][6] + a1.z + b1.z + bv1.z, 0.f);
                v1.w = fmaxf(acc[i][7] + a1.w + b1.w + bv1.w, 0.f);
                *(float4*)&C[(size_t)ro * 64 + n_off]     = v0;
                *(float4*)&C[(size_t)ro * 64 + n_off + 4] = v1;
            }
        }
    }
}

__global__ __launch_bounds__(256) void gemm_kernel(
        const float* __restrict__ A, const float* __restrict__ W,
        float* __restrict__ C, int M, int K, int Cn, int mode,
        const float* __restrict__ bias) {
    int bm = blockIdx.x * 128;
    int cof = blockIdx.y * 64;
    if (mode == 0)      gemm_body<0>(A, W, C, M, K, Cn, cof, Cn, bias, bm);
    else if (mode == 1) gemm_body<1>(A, W, C, M, K, Cn, cof, Cn, bias, bm);
    else                gemm_body<2>(A, W, C, M, K, Cn, cof, Cn, bias, bm);
}

__global__ __launch_bounds__(256) void gemm3_kernel(
        const float* __restrict__ A,
        const float* __restrict__ Ws, const float* __restrict__ Wd,
        const float* __restrict__ Wv, int M, int K) {
    int bm = blockIdx.x * 128;
    int y = blockIdx.y;
    if (y == 0)      gemm_body<0>(A, Ws, g_xsp, M, K, 64, 0, 64, nullptr, bm);
    else if (y == 1) gemm_body<0>(A, Wd, g_xdp, M, K, 64, 0, 64, nullptr, bm);
    else             gemm_body<0>(A, Wv, g_xv,  M, K, 128, (y - 2) * 64, 128, nullptr, bm);
}

// ---------------- node scalars (+ optional wae in last block) ----------------
__global__ void node_scalar_kernel(const float* __restrict__ xv, const float* __restrict__ a_s,
                                   const float* __restrict__ a_d, int D,
                                   const float* __restrict__ cWe, const float* __restrict__ a_e) {
    if (cWe && blockIdx.x == gridDim.x - 1) {
        for (int j = threadIdx.x; j < 512; j += blockDim.x) {
            int k = j >> 3, h = j & 7;
            const float* w = cWe + k * 128 + h * 16;
            const float* a = a_e + h * 16;
            float s = 0.f;
#pragma unroll
            for (int d = 0; d < 16; ++d) s = fmaf(w[d], a[d], s);
            g_wae[j] = s;
        }
        return;
    }
    int idx = blockIdx.x * blockDim.x + threadIdx.x;
    if (idx >= NN * 8) return;
    int node = idx >> 3, h = idx & 7;
    const float* xr = xv + (size_t)node * 8 * D + h * D;
    const float* as = a_s + h * D;
    const float* ad = a_d + h * D;
    float s1 = 0.f, s2 = 0.f;
    for (int d = 0; d < D; ++d) {
        float v = xr[d];
        s1 = fmaf(v, as[d], s1);
        s2 = fmaf(v, ad[d], s2);
    }
    g_ss[idx] = s1;
    g_sd[idx] = s2;
}

// ---------------- EGAT per-dst-node kernel (warp per node, single pass) --------
__global__ __launch_bounds__(256) void egat_node_kernel(
        const float* __restrict__ xv, const float* __restrict__ efc,
        const float* __restrict__ cWe, float* __restrict__ hout) {
    int gwarp = (blockIdx.x * blockDim.x + threadIdx.x) >> 5;
    int lane = threadIdx.x & 31;
    if (gwarp >= NN) return;
    int n = gwarp;
    int beg = g_off[n], end = g_off[n + 1];

    int h2 = lane >> 2;
    int kbase = (lane & 3) << 4;
    float sd2 = g_sd[n * 8 + h2];

    float wreg[16];
#pragma unroll
    for (int kk = 0; kk < 16; ++kk) wreg[kk] = g_wae[(kbase + kk) * 8 + h2];

    float sumex = 0.f;
    float av0 = 0.f, av1 = 0.f, av2 = 0.f, av3 = 0.f;
    float accT[16];
#pragma unroll
    for (int i = 0; i < 16; i++) accT[i] = 0.f;

#pragma unroll 2
    for (int i = beg; i < end; ++i) {
        int s = g_srcc[i];
        const float4* efr = (const float4*)&efc[(size_t)i * 64 + kbase];
        float4 e0 = efr[0], e1 = efr[1], e2 = efr[2], e3 = efr[3];
        float se = e0.x * wreg[0];
        se = fmaf(e0.y, wreg[1], se);  se = fmaf(e0.z, wreg[2], se);  se = fmaf(e0.w, wreg[3], se);
        se = fmaf(e1.x, wreg[4], se);  se = fmaf(e1.y, wreg[5], se);  se = fmaf(e1.z, wreg[6], se);
        se = fmaf(e1.w, wreg[7], se);  se = fmaf(e2.x, wreg[8], se);  se = fmaf(e2.y, wreg[9], se);
        se = fmaf(e2.z, wreg[10], se); se = fmaf(e2.w, wreg[11], se); se = fmaf(e3.x, wreg[12], se);
        se = fmaf(e3.y, wreg[13], se); se = fmaf(e3.z, wreg[14], se); se = fmaf(e3.w, wreg[15], se);
        se += __shfl_xor_sync(0xffffffffu, se, 1);
        se += __shfl_xor_sync(0xffffffffu, se, 2);

        float lg = lrelu(g_ss[s * 8 + h2] + sd2 + se);
        float ex = __expf(lg);
        sumex += ex;

        float4 xvv = *(const float4*)&xv[(size_t)s * 128 + (lane << 2)];
        av0 = fmaf(ex, xvv.x, av0);
        av1 = fmaf(ex, xvv.y, av1);
        av2 = fmaf(ex, xvv.z, av2);
        av3 = fmaf(ex, xvv.w, av3);
        accT[0]  = fmaf(ex, e0.x, accT[0]);  accT[1]  = fmaf(ex, e0.y, accT[1]);
        accT[2]  = fmaf(ex, e0.z, accT[2]);  accT[3]  = fmaf(ex, e0.w, accT[3]);
        accT[4]  = fmaf(ex, e1.x, accT[4]);  accT[5]  = fmaf(ex, e1.y, accT[5]);
        accT[6]  = fmaf(ex, e1.z, accT[6]);  accT[7]  = fmaf(ex, e1.w, accT[7]);
        accT[8]  = fmaf(ex, e2.x, accT[8]);  accT[9]  = fmaf(ex, e2.y, accT[9]);
        accT[10] = fmaf(ex, e2.z, accT[10]); accT[11] = fmaf(ex, e2.w, accT[11]);
        accT[12] = fmaf(ex, e3.x, accT[12]); accT[13] = fmaf(ex, e3.y, accT[13]);
        accT[14] = fmaf(ex, e3.z, accT[14]); accT[15] = fmaf(ex, e3.w, accT[15]);
    }

    float inv = 1.f / (sumex + 1e-16f);

    float4 ov;
    ov.x = elu1(av0 * inv); ov.y = elu1(av1 * inv);
    ov.z = elu1(av2 * inv); ov.w = elu1(av3 * inv);
    *(float4*)&hout[(size_t)n * 256 + (lane << 2)] = ov;

    float pd[16];
#pragma unroll
    for (int d = 0; d < 16; ++d) pd[d] = 0.f;
#pragma unroll
    for (int kk = 0; kk < 16; ++kk) {
        float t = accT[kk];
        const float* wr = &cWe[(size_t)(kbase + kk) * 128 + h2 * 16];
#pragma unroll
        for (int d = 0; d < 16; ++d) pd[d] = fmaf(t, wr[d], pd[d]);
    }
#pragma unroll
    for (int d = 0; d < 16; ++d) {
        pd[d] += __shfl_xor_sync(0xffffffffu, pd[d], 1);
        pd[d] += __shfl_xor_sync(0xffffffffu, pd[d], 2);
    }
    int sel = lane & 3;
    float o0, o1, o2, o3;
    if (sel == 0)      { o0 = pd[0];  o1 = pd[1];  o2 = pd[2];  o3 = pd[3]; }
    else if (sel == 1) { o0 = pd[4];  o1 = pd[5];  o2 = pd[6];  o3 = pd[7]; }
    else if (sel == 2) { o0 = pd[8];  o1 = pd[9];  o2 = pd[10]; o3 = pd[11]; }
    else               { o0 = pd[12]; o1 = pd[13]; o2 = pd[14]; o3 = pd[15]; }
    float4 on;
    on.x = elu1(o0 * inv); on.y = elu1(o1 * inv);
    on.z = elu1(o2 * inv); on.w = elu1(o3 * inv);
    *(float4*)&hout[(size_t)n * 256 + 128 + h2 * 16 + (sel << 2)] = on;
}

// ---------------- final GAT (concat=False -> mean over heads) ----------------
__global__ __launch_bounds__(256) void gat_node_kernel(
        const float* __restrict__ xg, const float* __restrict__ bias,
        float* __restrict__ out) {
    int gwarp = (blockIdx.x * blockDim.x + threadIdx.x) >> 5;
    int lane = threadIdx.x & 31;
    if (gwarp >= NN) return;
    int n = gwarp;
    int beg = g_off[n], end = g_off[n + 1];

    int h2 = lane >> 2;
    float sd2 = g_sd[n * 8 + h2];
    int c0 = (lane & 3) * 10;

    float acc[10];
#pragma unroll
    for (int j = 0; j < 10; j++) acc[j] = 0.f;
    float sumex = 0.f;

#pragma unroll 2
    for (int i = beg; i < end; ++i) {
        int s = g_srcc[i];
        float v = lrelu(g_ss[s * 8 + h2] + sd2);
        float ex = __expf(v);
        sumex += ex;
        const float* xr = &xg[(size_t)s * 320 + h2 * 40 + c0];
#pragma unroll
        for (int j = 0; j < 10; j += 2) {
            float2 t = *(const float2*)&xr[j];
            acc[j]     = fmaf(ex, t.x, acc[j]);
            acc[j + 1] = fmaf(ex, t.y, acc[j + 1]);
        }
    }
    float inv = 1.f / (sumex + 1e-16f);
#pragma unroll
    for (int j = 0; j < 10; ++j) {
        float v = acc[j] * inv;
        v += __shfl_xor_sync(0xffffffffu, v, 4);
        v += __shfl_xor_sync(0xffffffffu, v, 8);
        v += __shfl_xor_sync(0xffffffffu, v, 16);
        acc[j] = v;
    }
    if (lane < 4) {
#pragma unroll
        for (int j = 0; j < 10; ++j)
            out[(size_t)n * 40 + lane * 10 + j] = acc[j] * 0.125f + bias[lane * 10 + j];
    }
}

// ---------------- host ----------------
static inline dim3 ggrid(int M, int Cn) { return dim3((unsigned)((M + 127) / 128), (unsigned)(Cn / 64)); }

extern "C" void kernel_launch(void* const* d_in, const int* in_sizes, int n_in,
                              void* d_out, int out_size) {
    (void)in_sizes; (void)n_in; (void)out_size;
    const float* x     = (const float*)d_in[0];
    const int*   ei32  = (const int*)d_in[1];
    const float* ea    = (const float*)d_in[2];
    const float* e1_Ws = (const float*)d_in[3];
    const float* e1_Wd = (const float*)d_in[4];
    const float* e1_We = (const float*)d_in[5];
    const float* e1_b  = (const float*)d_in[6];
    const float* c1_Wv = (const float*)d_in[7];
    const float* c1_We = (const float*)d_in[8];
    const float* c1_as = (const float*)d_in[9];
    const float* c1_ad = (const float*)d_in[10];
    const float* c1_ae = (const float*)d_in[11];
    const float* e2_Ws = (const float*)d_in[12];
    const float* e2_Wd = (const float*)d_in[13];
    const float* e2_We = (const float*)d_in[14];
    const float* e2_b  = (const float*)d_in[15];
    const float* c2_Wv = (const float*)d_in[16];
    const float* c2_We = (const float*)d_in[17];
    const float* c2_as = (const float*)d_in[18];
    const float* c2_ad = (const float*)d_in[19];
    const float* c2_ae = (const float*)d_in[20];
    const float* g_Wp  = (const float*)d_in[21];
    const float* g_asP = (const float*)d_in[22];
    const float* g_adP = (const float*)d_in[23];
    const float* g_bP  = (const float*)d_in[24];
    float* out = (float*)d_out;

    void *p_efA, *p_efB, *p_xv, *p_h1, *p_h2, *p_xg;
    cudaGetSymbolAddress(&p_efA, g_efA);
    cudaGetSymbolAddress(&p_efB, g_efB);
    cudaGetSymbolAddress(&p_xv,  g_xv);
    cudaGetSymbolAddress(&p_h1,  g_h1);
    cudaGetSymbolAddress(&p_h2,  g_h2);
    cudaGetSymbolAddress(&p_xg,  g_xg);
    float* efA = (float*)p_efA; float* efB = (float*)p_efB;
    float* xv  = (float*)p_xv;  float* h1  = (float*)p_h1;
    float* h2  = (float*)p_h2;  float* xg  = (float*)p_xg;

    int nsgrid = (NN * 8 + 255) / 256 + 1;

    prep_kernel<<<(EE + 255) / 256, 256>>>(ei32);                               // 1
    count_kernel<<<(EE + 255) / 256, 256>>>();                                  // 2
    scan_kernel<<<1, 1024>>>();                                                 // 3
    // DIAGNOSTIC duplicate: true egat timing under ncu (captures my launch #4).
    // Writes g_xg (scratch here; overwritten by the final GEMM before any read).
    egat_node_kernel<<<(NN + 7) / 8, 256>>>(xv, efA, c1_We, xg);                // 4 <- ncu
    gemm3_kernel<<<dim3((NN + 127) / 128, 4), 256>>>(x, e1_Ws, e1_Wd, c1_Wv, NN, 128); // 5
    scatter_kernel<<<(EE + 255) / 256, 256>>>();                                // 6
    gemm_kernel<<<ggrid(EE, 64), 256>>>(ea, e1_We, efA, EE, 16, 64, 1, e1_b);   // 7
    node_scalar_kernel<<<nsgrid, 256>>>(xv, c1_as, c1_ad, 16, c1_We, c1_ae);    // 8
    egat_node_kernel<<<(NN + 7) / 8, 256>>>(xv, efA, c1_We, h1);                // 9

    gemm3_kernel<<<dim3((NN + 127) / 128, 4), 256>>>(h1, e2_Ws, e2_Wd, c2_Wv, NN, 256); // 10
    gemm_kernel<<<ggrid(EE, 64), 256>>>(efA, e2_We, efB, EE, 64, 64, 2, e2_b);  // 11
    node_scalar_kernel<<<nsgrid, 256>>>(xv, c2_as, c2_ad, 16, c2_We, c2_ae);    // 12
    egat_node_kernel<<<(NN + 7) / 8, 256>>>(xv, efB, c2_We, h2);                // 13

    gemm_kernel<<<ggrid(NN, 320), 256>>>(h2, g_Wp, xg, NN, 256, 320, 0, nullptr); // 14
    node_scalar_kernel<<<nsgrid - 1, 256>>>(xg, g_asP, g_adP, 40, nullptr, nullptr); // 15
    gat_node_kernel<<<(NN + 7) / 8, 256>>>(xg, g_bP, out);                      // 16
}

// round 10
// speedup vs baseline: 1.0559x; 1.0559x over previous
#include <cuda_runtime.h>
#include <math.h>
#include <stdint.h>
#include <stddef.h>

#define NN 50000
#define EE 800000

// ---------------- scratch (static __device__, no allocation) ----------------
static __device__ int   g_src[EE];
static __device__ int   g_dst[EE];
static __device__ int   g_pos[EE];
static __device__ int   g_srcc[EE];
static __device__ int   g_dstc[EE];
static __device__ int   g_deg[NN];
static __device__ int   g_off[NN + 1];
static __device__ int   g_cur[NN];
static __device__ float g_efA[(size_t)EE * 64];
static __device__ float g_efB[(size_t)EE * 64];
static __device__ float g_xsp[(size_t)NN * 64];
static __device__ float g_xdp[(size_t)NN * 64];
static __device__ float g_xv [(size_t)NN * 128];
static __device__ float g_ss [NN * 8];
static __device__ float g_sd [NN * 8];
static __device__ float g_h1 [(size_t)NN * 256];
static __device__ float g_h2 [(size_t)NN * 256];
static __device__ float g_xg [(size_t)NN * 320];
static __device__ float g_wae[64 * 8];

__device__ __forceinline__ float elu1(float x) { return x > 0.f ? x : expm1f(x); }
__device__ __forceinline__ float lrelu(float x) { return x > 0.f ? x : 0.2f * x; }

__device__ __forceinline__ void cp16(uint32_t dst, const void* src) {
    asm volatile("cp.async.ca.shared.global [%0], [%1], 16;" :: "r"(dst), "l"(src));
}

// ---------------- prep ----------------
__global__ void prep_kernel(const int* __restrict__ a32) {
    int tid = threadIdx.x;
    int nz = (tid < 256 && a32[2 * tid + 1] != 0) ? 1 : 0;
    int is64 = (__syncthreads_or(nz) == 0);
    int i = blockIdx.x * blockDim.x + tid;
    if (i < EE) {
        if (is64) {
            g_src[i] = a32[2 * (size_t)i];
            g_dst[i] = a32[2 * (size_t)EE + 2 * (size_t)i];
        } else {
            g_src[i] = a32[i];
            g_dst[i] = a32[(size_t)EE + i];
        }
    }
    if (i < NN) g_deg[i] = 0;
}

// ---------------- CSR build ----------------
__global__ void count_kernel() {
    int i = blockIdx.x * blockDim.x + threadIdx.x;
    if (i < EE) atomicAdd(&g_deg[g_dst[i]], 1);
}

__global__ void scan_kernel() {
    __shared__ int wsum[32];
    __shared__ int carry_s;
    int tid = threadIdx.x;
    int lane = tid & 31, wid = tid >> 5;
    if (tid == 0) carry_s = 0;
    __syncthreads();
    for (int base = 0; base < NN; base += 1024) {
        int i = base + tid;
        int v = (i < NN) ? g_deg[i] : 0;
        int x = v;
#pragma unroll
        for (int d = 1; d < 32; d <<= 1) {
            int t = __shfl_up_sync(0xffffffffu, x, d);
            if (lane >= d) x += t;
        }
        if (lane == 31) wsum[wid] = x;
        __syncthreads();
        if (wid == 0) {
            int w = wsum[lane];
            int y = w;
#pragma unroll
            for (int d = 1; d < 32; d <<= 1) {
                int t = __shfl_up_sync(0xffffffffu, y, d);
                if (lane >= d) y += t;
            }
            wsum[lane] = y - w;
        }
        __syncthreads();
        int carry = carry_s;
        int ex = carry + wsum[wid] + x - v;
        if (i < NN) { g_off[i] = ex; g_cur[i] = ex; }
        __syncthreads();
        if (tid == 1023) carry_s = carry + wsum[31] + x;
        __syncthreads();
    }
    if (tid == 0) g_off[NN] = carry_s;
}

__global__ void scatter_kernel() {
    int i = blockIdx.x * blockDim.x + threadIdx.x;
    if (i < EE) {
        int d = g_dst[i];
        int p = atomicAdd(&g_cur[d], 1);
        g_pos[i]  = p;
        g_srcc[p] = g_src[i];
        g_dstc[p] = d;
    }
}

// ---------------- GEMM core: 128x64 tile, 4x8 microtile ----------
template <int MODE>
__device__ __forceinline__ void gemm_body(
        const float* __restrict__ A, const float* __restrict__ W,
        float* __restrict__ C, int M, int K, int Wld, int cof, int Cld,
        const float* __restrict__ bias, int bm) {
    __shared__ float As[16][132];
    __shared__ float Bs[16][68];
    int tid = threadIdx.x;
    int wid = tid >> 5, lane = tid & 31;
    int wm = (wid & 3) * 32, wn = (wid >> 2) * 32;
    int m_off = wm + (lane & 7) * 4;
    int n_off = wn + (lane >> 3) * 8;

    float acc[4][8];
#pragma unroll
    for (int i = 0; i < 4; i++)
#pragma unroll
        for (int j = 0; j < 8; j++) acc[i][j] = 0.f;

    for (int k0 = 0; k0 < K; k0 += 16) {
#pragma unroll
        for (int t = tid; t < 512; t += 256) {
            int row = t >> 2, seg = t & 3;
            float4 av = make_float4(0.f, 0.f, 0.f, 0.f);
            if (bm + row < M) av = *(const float4*)&A[(size_t)(bm + row) * K + k0 + seg * 4];
            As[seg * 4 + 0][row] = av.x;
            As[seg * 4 + 1][row] = av.y;
            As[seg * 4 + 2][row] = av.z;
            As[seg * 4 + 3][row] = av.w;
        }
        {
            int kk = tid >> 4, ns = tid & 15;
            float4 wv = *(const float4*)&W[(size_t)(k0 + kk) * Wld + cof + ns * 4];
            *(float4*)&Bs[kk][ns * 4] = wv;
        }
        __syncthreads();
#pragma unroll
        for (int k = 0; k < 16; ++k) {
            float4 a  = *(const float4*)&As[k][m_off];
            float4 b0 = *(const float4*)&Bs[k][n_off];
            float4 b1 = *(const float4*)&Bs[k][n_off + 4];
            float am[4] = {a.x, a.y, a.z, a.w};
            float bv[8] = {b0.x, b0.y, b0.z, b0.w, b1.x, b1.y, b1.z, b1.w};
#pragma unroll
            for (int i = 0; i < 4; i++)
#pragma unroll
                for (int j = 0; j < 8; j++)
                    acc[i][j] = fmaf(am[i], bv[j], acc[i][j]);
        }
        __syncthreads();
    }

    if (MODE == 0) {
#pragma unroll
        for (int i = 0; i < 4; i++) {
            int r = bm + m_off + i;
            if (r < M) {
                float4 v0 = make_float4(acc[i][0], acc[i][1], acc[i][2], acc[i][3]);
                float4 v1 = make_float4(acc[i][4], acc[i][5], acc[i][6], acc[i][7]);
                *(float4*)&C[(size_t)r * Cld + cof + n_off]     = v0;
                *(float4*)&C[(size_t)r * Cld + cof + n_off + 4] = v1;
            }
        }
    } else {
        float4 bv0 = *(const float4*)&bias[n_off];
        float4 bv1 = *(const float4*)&bias[n_off + 4];
#pragma unroll
        for (int i = 0; i < 4; i++) {
            int r = bm + m_off + i;
            if (r < M) {
                int s, d, ro;
                if (MODE == 1) { s = g_src[r];  d = g_dst[r];  ro = g_pos[r]; }
                else           { s = g_srcc[r]; d = g_dstc[r]; ro = r; }
                float4 a0 = *(const float4*)&g_xsp[(size_t)s * 64 + n_off];
                float4 a1 = *(const float4*)&g_xsp[(size_t)s * 64 + n_off + 4];
                float4 b0 = *(const float4*)&g_xdp[(size_t)d * 64 + n_off];
                float4 b1 = *(const float4*)&g_xdp[(size_t)d * 64 + n_off + 4];
                float4 v0, v1;
                v0.x = fmaxf(acc[i][0] + a0.x + b0.x + bv0.x, 0.f);
                v0.y = fmaxf(acc[i][1] + a0.y + b0.y + bv0.y, 0.f);
                v0.z = fmaxf(acc[i][2] + a0.z + b0.z + bv0.z, 0.f);
                v0.w = fmaxf(acc[i][3] + a0.w + b0.w + bv0.w, 0.f);
                v1.x = fmaxf(acc[i][4] + a1.x + b1.x + bv1.x, 0.f);
                v1.y = fmaxf(acc[i][5] + a1.y + b1.y + bv1.y, 0.f);
                v1.z = fmaxf(acc[i][6] + a1.z + b1.z + bv1.z, 0.f);
                v1.w = fmaxf(acc[i][7] + a1.w + b1.w + bv1.w, 0.f);
                *(float4*)&C[(size_t)ro * 64 + n_off]     = v0;
                *(float4*)&C[(size_t)ro * 64 + n_off + 4] = v1;
            }
        }
    }
}

__global__ __launch_bounds__(256) void gemm_kernel(
        const float* __restrict__ A, const float* __restrict__ W,
        float* __restrict__ C, int M, int K, int Cn, int mode,
        const float* __restrict__ bias) {
    int bm = blockIdx.x * 128;
    int cof = blockIdx.y * 64;
    if (mode == 0)      gemm_body<0>(A, W, C, M, K, Cn, cof, Cn, bias, bm);
    else if (mode == 1) gemm_body<1>(A, W, C, M, K, Cn, cof, Cn, bias, bm);
    else                gemm_body<2>(A, W, C, M, K, Cn, cof, Cn, bias, bm);
}

__global__ __launch_bounds__(256) void gemm3_kernel(
        const float* __restrict__ A,
        const float* __restrict__ Ws, const float* __restrict__ Wd,
        const float* __restrict__ Wv, int M, int K) {
    int bm = blockIdx.x * 128;
    int y = blockIdx.y;
    if (y == 0)      gemm_body<0>(A, Ws, g_xsp, M, K, 64, 0, 64, nullptr, bm);
    else if (y == 1) gemm_body<0>(A, Wd, g_xdp, M, K, 64, 0, 64, nullptr, bm);
    else             gemm_body<0>(A, Wv, g_xv,  M, K, 128, (y - 2) * 64, 128, nullptr, bm);
}

// ---------------- node scalars (+ wae in last block) ----------------
__global__ void node_scalar_kernel(const float* __restrict__ xv, const float* __restrict__ a_s,
                                   const float* __restrict__ a_d, int D,
                                   const float* __restrict__ cWe, const float* __restrict__ a_e) {
    if (cWe && blockIdx.x == gridDim.x - 1) {
        for (int j = threadIdx.x; j < 512; j += blockDim.x) {
            int k = j >> 3, h = j & 7;
            const float* w = cWe + k * 128 + h * 16;
            const float* a = a_e + h * 16;
            float s = 0.f;
#pragma unroll
            for (int d = 0; d < 16; ++d) s = fmaf(w[d], a[d], s);
            g_wae[j] = s;
        }
        return;
    }
    int idx = blockIdx.x * blockDim.x + threadIdx.x;
    if (idx >= NN * 8) return;
    int node = idx >> 3, h = idx & 7;
    const float* xr = xv + (size_t)node * 8 * D + h * D;
    const float* as = a_s + h * D;
    const float* ad = a_d + h * D;
    float s1 = 0.f, s2 = 0.f;
    for (int d = 0; d < D; ++d) {
        float v = xr[d];
        s1 = fmaf(v, as[d], s1);
        s2 = fmaf(v, ad[d], s2);
    }
    g_ss[idx] = s1;
    g_sd[idx] = s2;
}

// ---------------- EGAT: warp/node + cp.async double-buffered ef staging -------
// Per warp: groups of 8 edges; ef rows (256B each) staged smem via LDGSTS; srcc
// batched via shfl; ss prefetched 8-deep; xv gather rotated 1 ahead.
__global__ __launch_bounds__(256) void egat_node_kernel(
        const float* __restrict__ xv, const float* __restrict__ efc,
        const float* __restrict__ cWe, float* __restrict__ hout) {
    __shared__ __align__(16) float sef[8][2][8][68];
    int gwarp = (blockIdx.x * blockDim.x + threadIdx.x) >> 5;
    int lane = threadIdx.x & 31;
    int wslot = (threadIdx.x >> 5);
    if (gwarp >= NN) return;
    int n = gwarp;
    int beg = g_off[n], end = g_off[n + 1];
    int deg = end - beg;
    int G = (deg + 7) >> 3;

    int h2 = lane >> 2;
    int kbase = (lane & 3) << 4;
    float sd2 = g_sd[n * 8 + h2];

    float wreg[16];
#pragma unroll
    for (int kk = 0; kk < 16; ++kk) wreg[kk] = g_wae[(kbase + kk) * 8 + h2];

    float sumex = 0.f;
    float av0 = 0.f, av1 = 0.f, av2 = 0.f, av3 = 0.f;
    float accT[16];
#pragma unroll
    for (int i = 0; i < 16; i++) accT[i] = 0.f;

    float* buf0 = &sef[wslot][0][0][0];
    float* buf1 = &sef[wslot][1][0][0];

    // initial prefetch: group 0
    if (G > 0) {
#pragma unroll
        for (int r = 0; r < 4; ++r) {
            int c = lane + r * 32;
            int e = c >> 4, p = c & 15;
            int i = beg + e;
            if (i < end) {
                uint32_t dst = (uint32_t)__cvta_generic_to_shared(buf0 + e * 68 + p * 4);
                cp16(dst, efc + (size_t)i * 64 + p * 4);
            }
        }
        asm volatile("cp.async.commit_group;");
    }

    for (int g = 0; g < G; ++g) {
        if (g + 1 < G) {
            float* nb = ((g + 1) & 1) ? buf1 : buf0;
            int nb0 = beg + (g + 1) * 8;
#pragma unroll
            for (int r = 0; r < 4; ++r) {
                int c = lane + r * 32;
                int e = c >> 4, p = c & 15;
                int i = nb0 + e;
                if (i < end) {
                    uint32_t dst = (uint32_t)__cvta_generic_to_shared(nb + e * 68 + p * 4);
                    cp16(dst, efc + (size_t)i * 64 + p * 4);
                }
            }
            asm volatile("cp.async.commit_group;");
            asm volatile("cp.async.wait_group 1;");
        } else {
            asm volatile("cp.async.wait_group 0;");
        }
        __syncwarp();

        float* eb = (g & 1) ? buf1 : buf0;
        int base = beg + g * 8;
        int nval = min(end - base, 8);

        int sv = (lane < nval) ? g_srcc[base + lane] : 0;
        int sj[8];
        float ssj[8];
#pragma unroll
        for (int j = 0; j < 8; ++j) sj[j] = __shfl_sync(0xffffffffu, sv, j);
#pragma unroll
        for (int j = 0; j < 8; ++j) ssj[j] = g_ss[sj[j] * 8 + h2];

        float4 xvn = *(const float4*)&xv[(size_t)sj[0] * 128 + (lane << 2)];

#pragma unroll
        for (int j = 0; j < 8; ++j) {
            if (j >= nval) break;
            float4 xvc = xvn;
            if (j + 1 < 8) xvn = *(const float4*)&xv[(size_t)sj[j + 1] * 128 + (lane << 2)];

            const float* er = eb + j * 68 + kbase;
            float4 e0 = *(const float4*)&er[0];
            float4 e1 = *(const float4*)&er[4];
            float4 e2 = *(const float4*)&er[8];
            float4 e3 = *(const float4*)&er[12];

            float se = e0.x * wreg[0];
            se = fmaf(e0.y, wreg[1], se);  se = fmaf(e0.z, wreg[2], se);  se = fmaf(e0.w, wreg[3], se);
            se = fmaf(e1.x, wreg[4], se);  se = fmaf(e1.y, wreg[5], se);  se = fmaf(e1.z, wreg[6], se);
            se = fmaf(e1.w, wreg[7], se);  se = fmaf(e2.x, wreg[8], se);  se = fmaf(e2.y, wreg[9], se);
            se = fmaf(e2.z, wreg[10], se); se = fmaf(e2.w, wreg[11], se); se = fmaf(e3.x, wreg[12], se);
            se = fmaf(e3.y, wreg[13], se); se = fmaf(e3.z, wreg[14], se); se = fmaf(e3.w, wreg[15], se);
            se += __shfl_xor_sync(0xffffffffu, se, 1);
            se += __shfl_xor_sync(0xffffffffu, se, 2);

            float ex = __expf(lrelu(ssj[j] + sd2 + se));
            sumex += ex;

            av0 = fmaf(ex, xvc.x, av0);
            av1 = fmaf(ex, xvc.y, av1);
            av2 = fmaf(ex, xvc.z, av2);
            av3 = fmaf(ex, xvc.w, av3);
            accT[0]  = fmaf(ex, e0.x, accT[0]);  accT[1]  = fmaf(ex, e0.y, accT[1]);
            accT[2]  = fmaf(ex, e0.z, accT[2]);  accT[3]  = fmaf(ex, e0.w, accT[3]);
            accT[4]  = fmaf(ex, e1.x, accT[4]);  accT[5]  = fmaf(ex, e1.y, accT[5]);
            accT[6]  = fmaf(ex, e1.z, accT[6]);  accT[7]  = fmaf(ex, e1.w, accT[7]);
            accT[8]  = fmaf(ex, e2.x, accT[8]);  accT[9]  = fmaf(ex, e2.y, accT[9]);
            accT[10] = fmaf(ex, e2.z, accT[10]); accT[11] = fmaf(ex, e2.w, accT[11]);
            accT[12] = fmaf(ex, e3.x, accT[12]); accT[13] = fmaf(ex, e3.y, accT[13]);
            accT[14] = fmaf(ex, e3.z, accT[14]); accT[15] = fmaf(ex, e3.w, accT[15]);
        }
        __syncwarp();   // protect buffer reuse (next prefetch overwrites eb)
    }

    float inv = 1.f / (sumex + 1e-16f);

    float4 ov;
    ov.x = elu1(av0 * inv); ov.y = elu1(av1 * inv);
    ov.z = elu1(av2 * inv); ov.w = elu1(av3 * inv);
    *(float4*)&hout[(size_t)n * 256 + (lane << 2)] = ov;

    float pd[16];
#pragma unroll
    for (int d = 0; d < 16; ++d) pd[d] = 0.f;
#pragma unroll
    for (int kk = 0; kk < 16; ++kk) {
        float t = accT[kk];
        const float* wr = &cWe[(size_t)(kbase + kk) * 128 + h2 * 16];
#pragma unroll
        for (int d = 0; d < 16; ++d) pd[d] = fmaf(t, wr[d], pd[d]);
    }
#pragma unroll
    for (int d = 0; d < 16; ++d) {
        pd[d] += __shfl_xor_sync(0xffffffffu, pd[d], 1);
        pd[d] += __shfl_xor_sync(0xffffffffu, pd[d], 2);
    }
    int sel = lane & 3;
    float o0, o1, o2, o3;
    if (sel == 0)      { o0 = pd[0];  o1 = pd[1];  o2 = pd[2];  o3 = pd[3]; }
    else if (sel == 1) { o0 = pd[4];  o1 = pd[5];  o2 = pd[6];  o3 = pd[7]; }
    else if (sel == 2) { o0 = pd[8];  o1 = pd[9];  o2 = pd[10]; o3 = pd[11]; }
    else               { o0 = pd[12]; o1 = pd[13]; o2 = pd[14]; o3 = pd[15]; }
    float4 on;
    on.x = elu1(o0 * inv); on.y = elu1(o1 * inv);
    on.z = elu1(o2 * inv); on.w = elu1(o3 * inv);
    *(float4*)&hout[(size_t)n * 256 + 128 + h2 * 16 + (sel << 2)] = on;
}

// ---------------- final GAT (mean over heads) with group prefetch ------------
__global__ __launch_bounds__(256) void gat_node_kernel(
        const float* __restrict__ xg, const float* __restrict__ bias,
        float* __restrict__ out) {
    int gwarp = (blockIdx.x * blockDim.x + threadIdx.x) >> 5;
    int lane = threadIdx.x & 31;
    if (gwarp >= NN) return;
    int n = gwarp;
    int beg = g_off[n], end = g_off[n + 1];
    int G = (end - beg + 7) >> 3;

    int h2 = lane >> 2;
    float sd2 = g_sd[n * 8 + h2];
    int c0 = (lane & 3) * 10;

    float acc[10];
#pragma unroll
    for (int j = 0; j < 10; j++) acc[j] = 0.f;
    float sumex = 0.f;

    for (int g = 0; g < G; ++g) {
        int base = beg + g * 8;
        int nval = min(end - base, 8);
        int sv = (lane < nval) ? g_srcc[base + lane] : 0;
        int sj[8];
        float ssj[8];
#pragma unroll
        for (int j = 0; j < 8; ++j) sj[j] = __shfl_sync(0xffffffffu, sv, j);
#pragma unroll
        for (int j = 0; j < 8; ++j) ssj[j] = g_ss[sj[j] * 8 + h2];

#pragma unroll
        for (int j = 0; j < 8; ++j) {
            if (j >= nval) break;
            float ex = __expf(lrelu(ssj[j] + sd2));
            sumex += ex;
            const float* xr = &xg[(size_t)sj[j] * 320 + h2 * 40 + c0];
#pragma unroll
            for (int q = 0; q < 10; q += 2) {
                float2 t = *(const float2*)&xr[q];
                acc[q]     = fmaf(ex, t.x, acc[q]);
                acc[q + 1] = fmaf(ex, t.y, acc[q + 1]);
            }
        }
    }
    float inv = 1.f / (sumex + 1e-16f);
#pragma unroll
    for (int j = 0; j < 10; ++j) {
        float v = acc[j] * inv;
        v += __shfl_xor_sync(0xffffffffu, v, 4);
        v += __shfl_xor_sync(0xffffffffu, v, 8);
        v += __shfl_xor_sync(0xffffffffu, v, 16);
        acc[j] = v;
    }
    if (lane < 4) {
#pragma unroll
        for (int j = 0; j < 10; ++j)
            out[(size_t)n * 40 + lane * 10 + j] = acc[j] * 0.125f + bias[lane * 10 + j];
    }
}

// ---------------- host ----------------
static inline dim3 ggrid(int M, int Cn) { return dim3((unsigned)((M + 127) / 128), (unsigned)(Cn / 64)); }

extern "C" void kernel_launch(void* const* d_in, const int* in_sizes, int n_in,
                              void* d_out, int out_size) {
    (void)in_sizes; (void)n_in; (void)out_size;
    const float* x     = (const float*)d_in[0];
    const int*   ei32  = (const int*)d_in[1];
    const float* ea    = (const float*)d_in[2];
    const float* e1_Ws = (const float*)d_in[3];
    const float* e1_Wd = (const float*)d_in[4];
    const float* e1_We = (const float*)d_in[5];
    const float* e1_b  = (const float*)d_in[6];
    const float* c1_Wv = (const float*)d_in[7];
    const float* c1_We = (const float*)d_in[8];
    const float* c1_as = (const float*)d_in[9];
    const float* c1_ad = (const float*)d_in[10];
    const float* c1_ae = (const float*)d_in[11];
    const float* e2_Ws = (const float*)d_in[12];
    const float* e2_Wd = (const float*)d_in[13];
    const float* e2_We = (const float*)d_in[14];
    const float* e2_b  = (const float*)d_in[15];
    const float* c2_Wv = (const float*)d_in[16];
    const float* c2_We = (const float*)d_in[17];
    const float* c2_as = (const float*)d_in[18];
    const float* c2_ad = (const float*)d_in[19];
    const float* c2_ae = (const float*)d_in[20];
    const float* g_Wp  = (const float*)d_in[21];
    const float* g_asP = (const float*)d_in[22];
    const float* g_adP = (const float*)d_in[23];
    const float* g_bP  = (const float*)d_in[24];
    float* out = (float*)d_out;

    void *p_efA, *p_efB, *p_xv, *p_h1, *p_h2, *p_xg;
    cudaGetSymbolAddress(&p_efA, g_efA);
    cudaGetSymbolAddress(&p_efB, g_efB);
    cudaGetSymbolAddress(&p_xv,  g_xv);
    cudaGetSymbolAddress(&p_h1,  g_h1);
    cudaGetSymbolAddress(&p_h2,  g_h2);
    cudaGetSymbolAddress(&p_xg,  g_xg);
    float* efA = (float*)p_efA; float* efB = (float*)p_efB;
    float* xv  = (float*)p_xv;  float* h1  = (float*)p_h1;
    float* h2  = (float*)p_h2;  float* xg  = (float*)p_xg;

    int nsgrid = (NN * 8 + 255) / 256 + 1;

    prep_kernel<<<(EE + 255) / 256, 256>>>(ei32);                               // 1
    count_kernel<<<(EE + 255) / 256, 256>>>();                                  // 2
    scan_kernel<<<1, 1024>>>();                                                 // 3
    // DIAGNOSTIC duplicate: measures NEW egat under ncu (slot 4). Writes g_xg
    // scratch; overwritten by the final GEMM before its only reader.
    egat_node_kernel<<<(NN + 7) / 8, 256>>>(xv, efA, c1_We, xg);                // 4 <- ncu
    gemm3_kernel<<<dim3((NN + 127) / 128, 4), 256>>>(x, e1_Ws, e1_Wd, c1_Wv, NN, 128); // 5
    scatter_kernel<<<(EE + 255) / 256, 256>>>();                                // 6
    gemm_kernel<<<ggrid(EE, 64), 256>>>(ea, e1_We, efA, EE, 16, 64, 1, e1_b);   // 7
    node_scalar_kernel<<<nsgrid, 256>>>(xv, c1_as, c1_ad, 16, c1_We, c1_ae);    // 8
    egat_node_kernel<<<(NN + 7) / 8, 256>>>(xv, efA, c1_We, h1);                // 9

    gemm3_kernel<<<dim3((NN + 127) / 128, 4), 256>>>(h1, e2_Ws, e2_Wd, c2_Wv, NN, 256); // 10
    gemm_kernel<<<ggrid(EE, 64), 256>>>(efA, e2_We, efB, EE, 64, 64, 2, e2_b);  // 11
    node_scalar_kernel<<<nsgrid, 256>>>(xv, c2_as, c2_ad, 16, c2_We, c2_ae);    // 12
    egat_node_kernel<<<(NN + 7) / 8, 256>>>(xv, efB, c2_We, h2);                // 13

    gemm_kernel<<<ggrid(NN, 320), 256>>>(h2, g_Wp, xg, NN, 256, 320, 0, nullptr); // 14
    node_scalar_kernel<<<nsgrid - 1, 256>>>(xg, g_asP, g_adP, 40, nullptr, nullptr); // 15
    gat_node_kernel<<<(NN + 7) / 8, 256>>>(xg, g_bP, out);                      // 16
}

// round 11
// speedup vs baseline: 1.8687x; 1.7699x over previous
#include <cuda_runtime.h>
#include <math.h>
#include <stdint.h>
#include <stddef.h>

#define NN 50000
#define EE 800000

// egat dynamic smem: ef staging (8 warps x 2 bufs x 8 edges x 68 floats) + sWe (8192 floats)
#define EGAT_STAGE_FLOATS (8 * 2 * 8 * 68)
#define EGAT_SMEM_BYTES ((EGAT_STAGE_FLOATS + 8192) * 4)

// ---------------- scratch (static __device__, no allocation) ----------------
static __device__ int   g_src[EE];
static __device__ int   g_dst[EE];
static __device__ int   g_pos[EE];
static __device__ int   g_srcc[EE];
static __device__ int   g_dstc[EE];
static __device__ int   g_deg[NN];
static __device__ int   g_off[NN + 1];
static __device__ int   g_cur[NN];
static __device__ float g_efA[(size_t)EE * 64];
static __device__ float g_efB[(size_t)EE * 64];
static __device__ float g_xsp[(size_t)NN * 64];
static __device__ float g_xdp[(size_t)NN * 64];
static __device__ float g_xv [(size_t)NN * 128];
static __device__ float g_ss [NN * 8];
static __device__ float g_sd [NN * 8];
static __device__ float g_h1 [(size_t)NN * 256];
static __device__ float g_h2 [(size_t)NN * 256];
static __device__ float g_xg [(size_t)NN * 320];
static __device__ float g_wae[64 * 8];

__device__ __forceinline__ float elu1(float x) { return x > 0.f ? x : expm1f(x); }
__device__ __forceinline__ float lrelu(float x) { return x > 0.f ? x : 0.2f * x; }

__device__ __forceinline__ void cp16(uint32_t dst, const void* src) {
    asm volatile("cp.async.ca.shared.global [%0], [%1], 16;" :: "r"(dst), "l"(src));
}

// ---------------- prep ----------------
__global__ void prep_kernel(const int* __restrict__ a32) {
    int tid = threadIdx.x;
    int nz = (tid < 256 && a32[2 * tid + 1] != 0) ? 1 : 0;
    int is64 = (__syncthreads_or(nz) == 0);
    int i = blockIdx.x * blockDim.x + tid;
    if (i < EE) {
        if (is64) {
            g_src[i] = a32[2 * (size_t)i];
            g_dst[i] = a32[2 * (size_t)EE + 2 * (size_t)i];
        } else {
            g_src[i] = a32[i];
            g_dst[i] = a32[(size_t)EE + i];
        }
    }
    if (i < NN) g_deg[i] = 0;
}

// ---------------- CSR build ----------------
__global__ void count_kernel() {
    int i = blockIdx.x * blockDim.x + threadIdx.x;
    if (i < EE) atomicAdd(&g_deg[g_dst[i]], 1);
}

__global__ void scan_kernel() {
    __shared__ int wsum[32];
    __shared__ int carry_s;
    int tid = threadIdx.x;
    int lane = tid & 31, wid = tid >> 5;
    if (tid == 0) carry_s = 0;
    __syncthreads();
    for (int base = 0; base < NN; base += 1024) {
        int i = base + tid;
        int v = (i < NN) ? g_deg[i] : 0;
        int x = v;
#pragma unroll
        for (int d = 1; d < 32; d <<= 1) {
            int t = __shfl_up_sync(0xffffffffu, x, d);
            if (lane >= d) x += t;
        }
        if (lane == 31) wsum[wid] = x;
        __syncthreads();
        if (wid == 0) {
            int w = wsum[lane];
            int y = w;
#pragma unroll
            for (int d = 1; d < 32; d <<= 1) {
                int t = __shfl_up_sync(0xffffffffu, y, d);
                if (lane >= d) y += t;
            }
            wsum[lane] = y - w;
        }
        __syncthreads();
        int carry = carry_s;
        int ex = carry + wsum[wid] + x - v;
        if (i < NN) { g_off[i] = ex; g_cur[i] = ex; }
        __syncthreads();
        if (tid == 1023) carry_s = carry + wsum[31] + x;
        __syncthreads();
    }
    if (tid == 0) g_off[NN] = carry_s;
}

__global__ void scatter_kernel() {
    int i = blockIdx.x * blockDim.x + threadIdx.x;
    if (i < EE) {
        int d = g_dst[i];
        int p = atomicAdd(&g_cur[d], 1);
        g_pos[i]  = p;
        g_srcc[p] = g_src[i];
        g_dstc[p] = d;
    }
}

// ---------------- GEMM core: 128x64 tile, 4x8 microtile ----------
template <int MODE>
__device__ __forceinline__ void gemm_body(
        const float* __restrict__ A, const float* __restrict__ W,
        float* __restrict__ C, int M, int K, int Wld, int cof, int Cld,
        const float* __restrict__ bias, int bm) {
    __shared__ float As[16][132];
    __shared__ float Bs[16][68];
    int tid = threadIdx.x;
    int wid = tid >> 5, lane = tid & 31;
    int wm = (wid & 3) * 32, wn = (wid >> 2) * 32;
    int m_off = wm + (lane & 7) * 4;
    int n_off = wn + (lane >> 3) * 8;

    float acc[4][8];
#pragma unroll
    for (int i = 0; i < 4; i++)
#pragma unroll
        for (int j = 0; j < 8; j++) acc[i][j] = 0.f;

    for (int k0 = 0; k0 < K; k0 += 16) {
#pragma unroll
        for (int t = tid; t < 512; t += 256) {
            int row = t >> 2, seg = t & 3;
            float4 av = make_float4(0.f, 0.f, 0.f, 0.f);
            if (bm + row < M) av = *(const float4*)&A[(size_t)(bm + row) * K + k0 + seg * 4];
            As[seg * 4 + 0][row] = av.x;
            As[seg * 4 + 1][row] = av.y;
            As[seg * 4 + 2][row] = av.z;
            As[seg * 4 + 3][row] = av.w;
        }
        {
            int kk = tid >> 4, ns = tid & 15;
            float4 wv = *(const float4*)&W[(size_t)(k0 + kk) * Wld + cof + ns * 4];
            *(float4*)&Bs[kk][ns * 4] = wv;
        }
        __syncthreads();
#pragma unroll
        for (int k = 0; k < 16; ++k) {
            float4 a  = *(const float4*)&As[k][m_off];
            float4 b0 = *(const float4*)&Bs[k][n_off];
            float4 b1 = *(const float4*)&Bs[k][n_off + 4];
            float am[4] = {a.x, a.y, a.z, a.w};
            float bv[8] = {b0.x, b0.y, b0.z, b0.w, b1.x, b1.y, b1.z, b1.w};
#pragma unroll
            for (int i = 0; i < 4; i++)
#pragma unroll
                for (int j = 0; j < 8; j++)
                    acc[i][j] = fmaf(am[i], bv[j], acc[i][j]);
        }
        __syncthreads();
    }

    if (MODE == 0) {
#pragma unroll
        for (int i = 0; i < 4; i++) {
            int r = bm + m_off + i;
            if (r < M) {
                float4 v0 = make_float4(acc[i][0], acc[i][1], acc[i][2], acc[i][3]);
                float4 v1 = make_float4(acc[i][4], acc[i][5], acc[i][6], acc[i][7]);
                *(float4*)&C[(size_t)r * Cld + cof + n_off]     = v0;
                *(float4*)&C[(size_t)r * Cld + cof + n_off + 4] = v1;
            }
        }
    } else {
        float4 bv0 = *(const float4*)&bias[n_off];
        float4 bv1 = *(const float4*)&bias[n_off + 4];
#pragma unroll
        for (int i = 0; i < 4; i++) {
            int r = bm + m_off + i;
            if (r < M) {
                int s, d, ro;
                if (MODE == 1) { s = g_src[r];  d = g_dst[r];  ro = g_pos[r]; }
                else           { s = g_srcc[r]; d = g_dstc[r]; ro = r; }
                float4 a0 = *(const float4*)&g_xsp[(size_t)s * 64 + n_off];
                float4 a1 = *(const float4*)&g_xsp[(size_t)s * 64 + n_off + 4];
                float4 b0 = *(const float4*)&g_xdp[(size_t)d * 64 + n_off];
                float4 b1 = *(const float4*)&g_xdp[(size_t)d * 64 + n_off + 4];
                float4 v0, v1;
                v0.x = fmaxf(acc[i][0] + a0.x + b0.x + bv0.x, 0.f);
                v0.y = fmaxf(acc[i][1] + a0.y + b0.y + bv0.y, 0.f);
                v0.z = fmaxf(acc[i][2] + a0.z + b0.z + bv0.z, 0.f);
                v0.w = fmaxf(acc[i][3] + a0.w + b0.w + bv0.w, 0.f);
                v1.x = fmaxf(acc[i][4] + a1.x + b1.x + bv1.x, 0.f);
                v1.y = fmaxf(acc[i][5] + a1.y + b1.y + bv1.y, 0.f);
                v1.z = fmaxf(acc[i][6] + a1.z + b1.z + bv1.z, 0.f);
                v1.w = fmaxf(acc[i][7] + a1.w + b1.w + bv1.w, 0.f);
                *(float4*)&C[(size_t)ro * 64 + n_off]     = v0;
                *(float4*)&C[(size_t)ro * 64 + n_off + 4] = v1;
            }
        }
    }
}

__global__ __launch_bounds__(256) void gemm_kernel(
        const float* __restrict__ A, const float* __restrict__ W,
        float* __restrict__ C, int M, int K, int Cn, int mode,
        const float* __restrict__ bias) {
    int bm = blockIdx.x * 128;
    int cof = blockIdx.y * 64;
    if (mode == 0)      gemm_body<0>(A, W, C, M, K, Cn, cof, Cn, bias, bm);
    else if (mode == 1) gemm_body<1>(A, W, C, M, K, Cn, cof, Cn, bias, bm);
    else                gemm_body<2>(A, W, C, M, K, Cn, cof, Cn, bias, bm);
}

__global__ __launch_bounds__(256) void gemm3_kernel(
        const float* __restrict__ A,
        const float* __restrict__ Ws, const float* __restrict__ Wd,
        const float* __restrict__ Wv, int M, int K) {
    int bm = blockIdx.x * 128;
    int y = blockIdx.y;
    if (y == 0)      gemm_body<0>(A, Ws, g_xsp, M, K, 64, 0, 64, nullptr, bm);
    else if (y == 1) gemm_body<0>(A, Wd, g_xdp, M, K, 64, 0, 64, nullptr, bm);
    else             gemm_body<0>(A, Wv, g_xv,  M, K, 128, (y - 2) * 64, 128, nullptr, bm);
}

// ---------------- node scalars (+ wae in last block) ----------------
__global__ void node_scalar_kernel(const float* __restrict__ xv, const float* __restrict__ a_s,
                                   const float* __restrict__ a_d, int D,
                                   const float* __restrict__ cWe, const float* __restrict__ a_e) {
    if (cWe && blockIdx.x == gridDim.x - 1) {
        for (int j = threadIdx.x; j < 512; j += blockDim.x) {
            int k = j >> 3, h = j & 7;
            const float* w = cWe + k * 128 + h * 16;
            const float* a = a_e + h * 16;
            float s = 0.f;
#pragma unroll
            for (int d = 0; d < 16; ++d) s = fmaf(w[d], a[d], s);
            g_wae[j] = s;
        }
        return;
    }
    int idx = blockIdx.x * blockDim.x + threadIdx.x;
    if (idx >= NN * 8) return;
    int node = idx >> 3, h = idx & 7;
    const float* xr = xv + (size_t)node * 8 * D + h * D;
    const float* as = a_s + h * D;
    const float* ad = a_d + h * D;
    float s1 = 0.f, s2 = 0.f;
    for (int d = 0; d < D; ++d) {
        float v = xr[d];
        s1 = fmaf(v, as[d], s1);
        s2 = fmaf(v, ad[d], s2);
    }
    g_ss[idx] = s1;
    g_sd[idx] = s2;
}

// ---------------- EGAT: warp/node, cp.async ef staging, smem-staged cWe -------
// Epilogue reads cWe from a per-block transposed smem copy:
//   sWe[(kk*16+d)*32 + (kb4*8+h2)]   (conflict-free: kb4*8+h2 is a lane permutation)
__global__ __launch_bounds__(256) void egat_node_kernel(
        const float* __restrict__ xv, const float* __restrict__ efc,
        const float* __restrict__ cWe, float* __restrict__ hout) {
    extern __shared__ __align__(16) float dyn[];
    float* stage = dyn;                       // EGAT_STAGE_FLOATS
    float* sWe   = dyn + EGAT_STAGE_FLOATS;   // 8192 floats

    // stage cWe (transposed, conflict-free layout) once per block
    for (int idx = threadIdx.x; idx < 8192; idx += 256) {
        int k = idx >> 7;        // 0..63
        int c = idx & 127;       // 0..127
        int h = c >> 4, d = c & 15;
        int kk = k & 15, kb4 = k >> 4;
        sWe[(kk * 16 + d) * 32 + kb4 * 8 + h] = cWe[idx];
    }
    __syncthreads();

    int gwarp = (blockIdx.x * blockDim.x + threadIdx.x) >> 5;   // exact fit: 6250*8 == NN
    int lane = threadIdx.x & 31;
    int wslot = (threadIdx.x >> 5);
    int n = gwarp;
    int beg = g_off[n], end = g_off[n + 1];
    int deg = end - beg;
    int G = (deg + 7) >> 3;

    int h2 = lane >> 2;
    int kbase = (lane & 3) << 4;
    int lid2 = (lane & 3) * 8 + h2;     // kb4*8 + h2
    float sd2 = g_sd[n * 8 + h2];

    float wreg[16];
#pragma unroll
    for (int kk = 0; kk < 16; ++kk) wreg[kk] = g_wae[(kbase + kk) * 8 + h2];

    float sumex = 0.f;
    float av0 = 0.f, av1 = 0.f, av2 = 0.f, av3 = 0.f;
    float accT[16];
#pragma unroll
    for (int i = 0; i < 16; i++) accT[i] = 0.f;

    float* buf0 = stage + wslot * 2 * 8 * 68;
    float* buf1 = buf0 + 8 * 68;

    if (G > 0) {
#pragma unroll
        for (int r = 0; r < 4; ++r) {
            int c = lane + r * 32;
            int e = c >> 4, p = c & 15;
            int i = beg + e;
            if (i < end) {
                uint32_t dst = (uint32_t)__cvta_generic_to_shared(buf0 + e * 68 + p * 4);
                cp16(dst, efc + (size_t)i * 64 + p * 4);
            }
        }
        asm volatile("cp.async.commit_group;");
    }

    for (int g = 0; g < G; ++g) {
        if (g + 1 < G) {
            float* nb = ((g + 1) & 1) ? buf1 : buf0;
            int nb0 = beg + (g + 1) * 8;
#pragma unroll
            for (int r = 0; r < 4; ++r) {
                int c = lane + r * 32;
                int e = c >> 4, p = c & 15;
                int i = nb0 + e;
                if (i < end) {
                    uint32_t dst = (uint32_t)__cvta_generic_to_shared(nb + e * 68 + p * 4);
                    cp16(dst, efc + (size_t)i * 64 + p * 4);
                }
            }
            asm volatile("cp.async.commit_group;");
            asm volatile("cp.async.wait_group 1;");
        } else {
            asm volatile("cp.async.wait_group 0;");
        }
        __syncwarp();

        float* eb = (g & 1) ? buf1 : buf0;
        int base = beg + g * 8;
        int nval = min(end - base, 8);

        int sv = (lane < nval) ? g_srcc[base + lane] : 0;
        int sj[8];
        float ssj[8];
#pragma unroll
        for (int j = 0; j < 8; ++j) sj[j] = __shfl_sync(0xffffffffu, sv, j);
#pragma unroll
        for (int j = 0; j < 8; ++j) ssj[j] = g_ss[sj[j] * 8 + h2];

        float4 xvn = *(const float4*)&xv[(size_t)sj[0] * 128 + (lane << 2)];

#pragma unroll
        for (int j = 0; j < 8; ++j) {
            if (j >= nval) break;
            float4 xvc = xvn;
            if (j + 1 < 8) xvn = *(const float4*)&xv[(size_t)sj[j + 1] * 128 + (lane << 2)];

            const float* er = eb + j * 68 + kbase;
            float4 e0 = *(const float4*)&er[0];
            float4 e1 = *(const float4*)&er[4];
            float4 e2 = *(const float4*)&er[8];
            float4 e3 = *(const float4*)&er[12];

            float se = e0.x * wreg[0];
            se = fmaf(e0.y, wreg[1], se);  se = fmaf(e0.z, wreg[2], se);  se = fmaf(e0.w, wreg[3], se);
            se = fmaf(e1.x, wreg[4], se);  se = fmaf(e1.y, wreg[5], se);  se = fmaf(e1.z, wreg[6], se);
            se = fmaf(e1.w, wreg[7], se);  se = fmaf(e2.x, wreg[8], se);  se = fmaf(e2.y, wreg[9], se);
            se = fmaf(e2.z, wreg[10], se); se = fmaf(e2.w, wreg[11], se); se = fmaf(e3.x, wreg[12], se);
            se = fmaf(e3.y, wreg[13], se); se = fmaf(e3.z, wreg[14], se); se = fmaf(e3.w, wreg[15], se);
            se += __shfl_xor_sync(0xffffffffu, se, 1);
            se += __shfl_xor_sync(0xffffffffu, se, 2);

            float ex = __expf(lrelu(ssj[j] + sd2 + se));
            sumex += ex;

            av0 = fmaf(ex, xvc.x, av0);
            av1 = fmaf(ex, xvc.y, av1);
            av2 = fmaf(ex, xvc.z, av2);
            av3 = fmaf(ex, xvc.w, av3);
            accT[0]  = fmaf(ex, e0.x, accT[0]);  accT[1]  = fmaf(ex, e0.y, accT[1]);
            accT[2]  = fmaf(ex, e0.z, accT[2]);  accT[3]  = fmaf(ex, e0.w, accT[3]);
            accT[4]  = fmaf(ex, e1.x, accT[4]);  accT[5]  = fmaf(ex, e1.y, accT[5]);
            accT[6]  = fmaf(ex, e1.z, accT[6]);  accT[7]  = fmaf(ex, e1.w, accT[7]);
            accT[8]  = fmaf(ex, e2.x, accT[8]);  accT[9]  = fmaf(ex, e2.y, accT[9]);
            accT[10] = fmaf(ex, e2.z, accT[10]); accT[11] = fmaf(ex, e2.w, accT[11]);
            accT[12] = fmaf(ex, e3.x, accT[12]); accT[13] = fmaf(ex, e3.y, accT[13]);
            accT[14] = fmaf(ex, e3.z, accT[14]); accT[15] = fmaf(ex, e3.w, accT[15]);
        }
        __syncwarp();
    }

    float inv = 1.f / (sumex + 1e-16f);

    float4 ov;
    ov.x = elu1(av0 * inv); ov.y = elu1(av1 * inv);
    ov.z = elu1(av2 * inv); ov.w = elu1(av3 * inv);
    *(float4*)&hout[(size_t)n * 256 + (lane << 2)] = ov;

    // epilogue: conflict-free smem reads of transposed cWe
    float pd[16];
#pragma unroll
    for (int d = 0; d < 16; ++d) pd[d] = 0.f;
#pragma unroll
    for (int kk = 0; kk < 16; ++kk) {
        float t = accT[kk];
        const float* wr = &sWe[kk * 16 * 32 + lid2];
#pragma unroll
        for (int d = 0; d < 16; ++d) pd[d] = fmaf(t, wr[d * 32], pd[d]);
    }
#pragma unroll
    for (int d = 0; d < 16; ++d) {
        pd[d] += __shfl_xor_sync(0xffffffffu, pd[d], 1);
        pd[d] += __shfl_xor_sync(0xffffffffu, pd[d], 2);
    }
    int sel = lane & 3;
    float o0, o1, o2, o3;
    if (sel == 0)      { o0 = pd[0];  o1 = pd[1];  o2 = pd[2];  o3 = pd[3]; }
    else if (sel == 1) { o0 = pd[4];  o1 = pd[5];  o2 = pd[6];  o3 = pd[7]; }
    else if (sel == 2) { o0 = pd[8];  o1 = pd[9];  o2 = pd[10]; o3 = pd[11]; }
    else               { o0 = pd[12]; o1 = pd[13]; o2 = pd[14]; o3 = pd[15]; }
    float4 on;
    on.x = elu1(o0 * inv); on.y = elu1(o1 * inv);
    on.z = elu1(o2 * inv); on.w = elu1(o3 * inv);
    *(float4*)&hout[(size_t)n * 256 + 128 + h2 * 16 + (sel << 2)] = on;
}

// ---------------- final GAT (mean over heads) with group prefetch ------------
__global__ __launch_bounds__(256) void gat_node_kernel(
        const float* __restrict__ xg, const float* __restrict__ bias,
        float* __restrict__ out) {
    int gwarp = (blockIdx.x * blockDim.x + threadIdx.x) >> 5;
    int lane = threadIdx.x & 31;
    if (gwarp >= NN) return;
    int n = gwarp;
    int beg = g_off[n], end = g_off[n + 1];
    int G = (end - beg + 7) >> 3;

    int h2 = lane >> 2;
    float sd2 = g_sd[n * 8 + h2];
    int c0 = (lane & 3) * 10;

    float acc[10];
#pragma unroll
    for (int j = 0; j < 10; j++) acc[j] = 0.f;
    float sumex = 0.f;

    for (int g = 0; g < G; ++g) {
        int base = beg + g * 8;
        int nval = min(end - base, 8);
        int sv = (lane < nval) ? g_srcc[base + lane] : 0;
        int sj[8];
        float ssj[8];
#pragma unroll
        for (int j = 0; j < 8; ++j) sj[j] = __shfl_sync(0xffffffffu, sv, j);
#pragma unroll
        for (int j = 0; j < 8; ++j) ssj[j] = g_ss[sj[j] * 8 + h2];

#pragma unroll
        for (int j = 0; j < 8; ++j) {
            if (j >= nval) break;
            float ex = __expf(lrelu(ssj[j] + sd2));
            sumex += ex;
            const float* xr = &xg[(size_t)sj[j] * 320 + h2 * 40 + c0];
#pragma unroll
            for (int q = 0; q < 10; q += 2) {
                float2 t = *(const float2*)&xr[q];
                acc[q]     = fmaf(ex, t.x, acc[q]);
                acc[q + 1] = fmaf(ex, t.y, acc[q + 1]);
            }
        }
    }
    float inv = 1.f / (sumex + 1e-16f);
#pragma unroll
    for (int j = 0; j < 10; ++j) {
        float v = acc[j] * inv;
        v += __shfl_xor_sync(0xffffffffu, v, 4);
        v += __shfl_xor_sync(0xffffffffu, v, 8);
        v += __shfl_xor_sync(0xffffffffu, v, 16);
        acc[j] = v;
    }
    if (lane < 4) {
#pragma unroll
        for (int j = 0; j < 10; ++j)
            out[(size_t)n * 40 + lane * 10 + j] = acc[j] * 0.125f + bias[lane * 10 + j];
    }
}

// ---------------- host ----------------
static inline dim3 ggrid(int M, int Cn) { return dim3((unsigned)((M + 127) / 128), (unsigned)(Cn / 64)); }

extern "C" void kernel_launch(void* const* d_in, const int* in_sizes, int n_in,
                              void* d_out, int out_size) {
    (void)in_sizes; (void)n_in; (void)out_size;
    const float* x     = (const float*)d_in[0];
    const int*   ei32  = (const int*)d_in[1];
    const float* ea    = (const float*)d_in[2];
    const float* e1_Ws = (const float*)d_in[3];
    const float* e1_Wd = (const float*)d_in[4];
    const float* e1_We = (const float*)d_in[5];
    const float* e1_b  = (const float*)d_in[6];
    const float* c1_Wv = (const float*)d_in[7];
    const float* c1_We = (const float*)d_in[8];
    const float* c1_as = (const float*)d_in[9];
    const float* c1_ad = (const float*)d_in[10];
    const float* c1_ae = (const float*)d_in[11];
    const float* e2_Ws = (const float*)d_in[12];
    const float* e2_Wd = (const float*)d_in[13];
    const float* e2_We = (const float*)d_in[14];
    const float* e2_b  = (const float*)d_in[15];
    const float* c2_Wv = (const float*)d_in[16];
    const float* c2_We = (const float*)d_in[17];
    const float* c2_as = (const float*)d_in[18];
    const float* c2_ad = (const float*)d_in[19];
    const float* c2_ae = (const float*)d_in[20];
    const float* g_Wp  = (const float*)d_in[21];
    const float* g_asP = (const float*)d_in[22];
    const float* g_adP = (const float*)d_in[23];
    const float* g_bP  = (const float*)d_in[24];
    float* out = (float*)d_out;

    void *p_efA, *p_efB, *p_xv, *p_h1, *p_h2, *p_xg;
    cudaGetSymbolAddress(&p_efA, g_efA);
    cudaGetSymbolAddress(&p_efB, g_efB);
    cudaGetSymbolAddress(&p_xv,  g_xv);
    cudaGetSymbolAddress(&p_h1,  g_h1);
    cudaGetSymbolAddress(&p_h2,  g_h2);
    cudaGetSymbolAddress(&p_xg,  g_xg);
    float* efA = (float*)p_efA; float* efB = (float*)p_efB;
    float* xv  = (float*)p_xv;  float* h1  = (float*)p_h1;
    float* h2  = (float*)p_h2;  float* xg  = (float*)p_xg;

    cudaFuncSetAttribute(egat_node_kernel,
                         cudaFuncAttributeMaxDynamicSharedMemorySize, EGAT_SMEM_BYTES);

    int nsgrid = (NN * 8 + 255) / 256 + 1;

    prep_kernel<<<(EE + 255) / 256, 256>>>(ei32);                               // 1
    count_kernel<<<(EE + 255) / 256, 256>>>();                                  // 2
    scan_kernel<<<1, 1024>>>();                                                 // 3
    // DIAGNOSTIC duplicate: measures NEW egat under ncu (slot 4). Writes g_xg
    // scratch; overwritten by the final GEMM before its only reader.
    egat_node_kernel<<<(NN + 7) / 8, 256, EGAT_SMEM_BYTES>>>(xv, efA, c1_We, xg); // 4 <- ncu
    gemm3_kernel<<<dim3((NN + 127) / 128, 4), 256>>>(x, e1_Ws, e1_Wd, c1_Wv, NN, 128); // 5
    scatter_kernel<<<(EE + 255) / 256, 256>>>();                                // 6
    gemm_kernel<<<ggrid(EE, 64), 256>>>(ea, e1_We, efA, EE, 16, 64, 1, e1_b);   // 7
    node_scalar_kernel<<<nsgrid, 256>>>(xv, c1_as, c1_ad, 16, c1_We, c1_ae);    // 8
    egat_node_kernel<<<(NN + 7) / 8, 256, EGAT_SMEM_BYTES>>>(xv, efA, c1_We, h1); // 9

    gemm3_kernel<<<dim3((NN + 127) / 128, 4), 256>>>(h1, e2_Ws, e2_Wd, c2_Wv, NN, 256); // 10
    gemm_kernel<<<ggrid(EE, 64), 256>>>(efA, e2_We, efB, EE, 64, 64, 2, e2_b);  // 11
    node_scalar_kernel<<<nsgrid, 256>>>(xv, c2_as, c2_ad, 16, c2_We, c2_ae);    // 12
    egat_node_kernel<<<(NN + 7) / 8, 256, EGAT_SMEM_BYTES>>>(xv, efB, c2_We, h2); // 13

    gemm_kernel<<<ggrid(NN, 320), 256>>>(h2, g_Wp, xg, NN, 256, 320, 0, nullptr); // 14
    node_scalar_kernel<<<nsgrid - 1, 256>>>(xg, g_asP, g_adP, 40, nullptr, nullptr); // 15
    gat_node_kernel<<<(NN + 7) / 8, 256>>>(xg, g_bP, out);                      // 16
}

// round 12
// speedup vs baseline: 2.2472x; 1.2025x over previous
#include <cuda_runtime.h>
#include <math.h>
#include <stdint.h>
#include <stddef.h>

#define NN 50000
#define EE 800000

// egat dynamic smem: ef staging (8 warps x 2 bufs x 8 edges x 80 floats) + sWe (8192 floats)
// ef row = 4 chunks of 16 floats at stride 20 (4-float pad) -> conflict-free LDS
#define EGAT_ROWF 80
#define EGAT_STAGE_FLOATS (8 * 2 * 8 * EGAT_ROWF)
#define EGAT_SMEM_BYTES ((EGAT_STAGE_FLOATS + 8192) * 4)

// ---------------- scratch (static __device__, no allocation) ----------------
static __device__ int   g_src[EE];
static __device__ int   g_dst[EE];
static __device__ int   g_pos[EE];
static __device__ int   g_srcc[EE];
static __device__ int   g_dstc[EE];
static __device__ int   g_deg[NN];
static __device__ int   g_off[NN + 1];
static __device__ int   g_cur[NN];
static __device__ float g_efA[(size_t)EE * 64];
static __device__ float g_efB[(size_t)EE * 64];
static __device__ float g_xsp[(size_t)NN * 64];
static __device__ float g_xdp[(size_t)NN * 64];
static __device__ float g_xv [(size_t)NN * 128];
static __device__ float g_ss [NN * 8];
static __device__ float g_sd [NN * 8];
static __device__ float g_h1 [(size_t)NN * 256];
static __device__ float g_h2 [(size_t)NN * 256];
static __device__ float g_xg [(size_t)NN * 320];
static __device__ float g_wae[64 * 8];

__device__ __forceinline__ float elu1(float x) { return x > 0.f ? x : expm1f(x); }
__device__ __forceinline__ float lrelu(float x) { return x > 0.f ? x : 0.2f * x; }

__device__ __forceinline__ void cp16(uint32_t dst, const void* src) {
    asm volatile("cp.async.ca.shared.global [%0], [%1], 16;" :: "r"(dst), "l"(src));
}

// ---------------- prep ----------------
__global__ void prep_kernel(const int* __restrict__ a32) {
    int tid = threadIdx.x;
    int nz = (tid < 256 && a32[2 * tid + 1] != 0) ? 1 : 0;
    int is64 = (__syncthreads_or(nz) == 0);
    int i = blockIdx.x * blockDim.x + tid;
    if (i < EE) {
        if (is64) {
            g_src[i] = a32[2 * (size_t)i];
            g_dst[i] = a32[2 * (size_t)EE + 2 * (size_t)i];
        } else {
            g_src[i] = a32[i];
            g_dst[i] = a32[(size_t)EE + i];
        }
    }
    if (i < NN) g_deg[i] = 0;
}

// ---------------- CSR build ----------------
__global__ void count_kernel() {
    int i = blockIdx.x * blockDim.x + threadIdx.x;
    if (i < EE) atomicAdd(&g_deg[g_dst[i]], 1);
}

__global__ void scan_kernel() {
    __shared__ int wsum[32];
    __shared__ int carry_s;
    int tid = threadIdx.x;
    int lane = tid & 31, wid = tid >> 5;
    if (tid == 0) carry_s = 0;
    __syncthreads();
    for (int base = 0; base < NN; base += 1024) {
        int i = base + tid;
        int v = (i < NN) ? g_deg[i] : 0;
        int x = v;
#pragma unroll
        for (int d = 1; d < 32; d <<= 1) {
            int t = __shfl_up_sync(0xffffffffu, x, d);
            if (lane >= d) x += t;
        }
        if (lane == 31) wsum[wid] = x;
        __syncthreads();
        if (wid == 0) {
            int w = wsum[lane];
            int y = w;
#pragma unroll
            for (int d = 1; d < 32; d <<= 1) {
                int t = __shfl_up_sync(0xffffffffu, y, d);
                if (lane >= d) y += t;
            }
            wsum[lane] = y - w;
        }
        __syncthreads();
        int carry = carry_s;
        int ex = carry + wsum[wid] + x - v;
        if (i < NN) { g_off[i] = ex; g_cur[i] = ex; }
        __syncthreads();
        if (tid == 1023) carry_s = carry + wsum[31] + x;
        __syncthreads();
    }
    if (tid == 0) g_off[NN] = carry_s;
}

__global__ void scatter_kernel() {
    int i = blockIdx.x * blockDim.x + threadIdx.x;
    if (i < EE) {
        int d = g_dst[i];
        int p = atomicAdd(&g_cur[d], 1);
        g_pos[i]  = p;
        g_srcc[p] = g_src[i];
        g_dstc[p] = d;
    }
}

// ---------------- GEMM core: 128x64 tile, 4x8 microtile ----------
template <int MODE>
__device__ __forceinline__ void gemm_body(
        const float* __restrict__ A, const float* __restrict__ W,
        float* __restrict__ C, int M, int K, int Wld, int cof, int Cld,
        const float* __restrict__ bias, int bm) {
    __shared__ float As[16][132];
    __shared__ float Bs[16][68];
    int tid = threadIdx.x;
    int wid = tid >> 5, lane = tid & 31;
    int wm = (wid & 3) * 32, wn = (wid >> 2) * 32;
    int m_off = wm + (lane & 7) * 4;
    int n_off = wn + (lane >> 3) * 8;

    float acc[4][8];
#pragma unroll
    for (int i = 0; i < 4; i++)
#pragma unroll
        for (int j = 0; j < 8; j++) acc[i][j] = 0.f;

    for (int k0 = 0; k0 < K; k0 += 16) {
#pragma unroll
        for (int t = tid; t < 512; t += 256) {
            int row = t >> 2, seg = t & 3;
            float4 av = make_float4(0.f, 0.f, 0.f, 0.f);
            if (bm + row < M) av = *(const float4*)&A[(size_t)(bm + row) * K + k0 + seg * 4];
            As[seg * 4 + 0][row] = av.x;
            As[seg * 4 + 1][row] = av.y;
            As[seg * 4 + 2][row] = av.z;
            As[seg * 4 + 3][row] = av.w;
        }
        {
            int kk = tid >> 4, ns = tid & 15;
            float4 wv = *(const float4*)&W[(size_t)(k0 + kk) * Wld + cof + ns * 4];
            *(float4*)&Bs[kk][ns * 4] = wv;
        }
        __syncthreads();
#pragma unroll
        for (int k = 0; k < 16; ++k) {
            float4 a  = *(const float4*)&As[k][m_off];
            float4 b0 = *(const float4*)&Bs[k][n_off];
            float4 b1 = *(const float4*)&Bs[k][n_off + 4];
            float am[4] = {a.x, a.y, a.z, a.w};
            float bv[8] = {b0.x, b0.y, b0.z, b0.w, b1.x, b1.y, b1.z, b1.w};
#pragma unroll
            for (int i = 0; i < 4; i++)
#pragma unroll
                for (int j = 0; j < 8; j++)
                    acc[i][j] = fmaf(am[i], bv[j], acc[i][j]);
        }
        __syncthreads();
    }

    if (MODE == 0) {
#pragma unroll
        for (int i = 0; i < 4; i++) {
            int r = bm + m_off + i;
            if (r < M) {
                float4 v0 = make_float4(acc[i][0], acc[i][1], acc[i][2], acc[i][3]);
                float4 v1 = make_float4(acc[i][4], acc[i][5], acc[i][6], acc[i][7]);
                *(float4*)&C[(size_t)r * Cld + cof + n_off]     = v0;
                *(float4*)&C[(size_t)r * Cld + cof + n_off + 4] = v1;
            }
        }
    } else {
        float4 bv0 = *(const float4*)&bias[n_off];
        float4 bv1 = *(const float4*)&bias[n_off + 4];
#pragma unroll
        for (int i = 0; i < 4; i++) {
            int r = bm + m_off + i;
            if (r < M) {
                int s, d, ro;
                if (MODE == 1) { s = g_src[r];  d = g_dst[r];  ro = g_pos[r]; }
                else           { s = g_srcc[r]; d = g_dstc[r]; ro = r; }
                float4 a0 = *(const float4*)&g_xsp[(size_t)s * 64 + n_off];
                float4 a1 = *(const float4*)&g_xsp[(size_t)s * 64 + n_off + 4];
                float4 b0 = *(const float4*)&g_xdp[(size_t)d * 64 + n_off];
                float4 b1 = *(const float4*)&g_xdp[(size_t)d * 64 + n_off + 4];
                float4 v0, v1;
                v0.x = fmaxf(acc[i][0] + a0.x + b0.x + bv0.x, 0.f);
                v0.y = fmaxf(acc[i][1] + a0.y + b0.y + bv0.y, 0.f);
                v0.z = fmaxf(acc[i][2] + a0.z + b0.z + bv0.z, 0.f);
                v0.w = fmaxf(acc[i][3] + a0.w + b0.w + bv0.w, 0.f);
                v1.x = fmaxf(acc[i][4] + a1.x + b1.x + bv1.x, 0.f);
                v1.y = fmaxf(acc[i][5] + a1.y + b1.y + bv1.y, 0.f);
                v1.z = fmaxf(acc[i][6] + a1.z + b1.z + bv1.z, 0.f);
                v1.w = fmaxf(acc[i][7] + a1.w + b1.w + bv1.w, 0.f);
                *(float4*)&C[(size_t)ro * 64 + n_off]     = v0;
                *(float4*)&C[(size_t)ro * 64 + n_off + 4] = v1;
            }
        }
    }
}

__global__ __launch_bounds__(256) void gemm_kernel(
        const float* __restrict__ A, const float* __restrict__ W,
        float* __restrict__ C, int M, int K, int Cn, int mode,
        const float* __restrict__ bias) {
    int bm = blockIdx.x * 128;
    int cof = blockIdx.y * 64;
    if (mode == 0)      gemm_body<0>(A, W, C, M, K, Cn, cof, Cn, bias, bm);
    else if (mode == 1) gemm_body<1>(A, W, C, M, K, Cn, cof, Cn, bias, bm);
    else                gemm_body<2>(A, W, C, M, K, Cn, cof, Cn, bias, bm);
}

__global__ __launch_bounds__(256) void gemm3_kernel(
        const float* __restrict__ A,
        const float* __restrict__ Ws, const float* __restrict__ Wd,
        const float* __restrict__ Wv, int M, int K) {
    int bm = blockIdx.x * 128;
    int y = blockIdx.y;
    if (y == 0)      gemm_body<0>(A, Ws, g_xsp, M, K, 64, 0, 64, nullptr, bm);
    else if (y == 1) gemm_body<0>(A, Wd, g_xdp, M, K, 64, 0, 64, nullptr, bm);
    else             gemm_body<0>(A, Wv, g_xv,  M, K, 128, (y - 2) * 64, 128, nullptr, bm);
}

// ---------------- node scalars (+ wae in last block) ----------------
__global__ void node_scalar_kernel(const float* __restrict__ xv, const float* __restrict__ a_s,
                                   const float* __restrict__ a_d, int D,
                                   const float* __restrict__ cWe, const float* __restrict__ a_e) {
    if (cWe && blockIdx.x == gridDim.x - 1) {
        for (int j = threadIdx.x; j < 512; j += blockDim.x) {
            int k = j >> 3, h = j & 7;
            const float* w = cWe + k * 128 + h * 16;
            const float* a = a_e + h * 16;
            float s = 0.f;
#pragma unroll
            for (int d = 0; d < 16; ++d) s = fmaf(w[d], a[d], s);
            g_wae[j] = s;
        }
        return;
    }
    int idx = blockIdx.x * blockDim.x + threadIdx.x;
    if (idx >= NN * 8) return;
    int node = idx >> 3, h = idx & 7;
    const float* xr = xv + (size_t)node * 8 * D + h * D;
    const float* as = a_s + h * D;
    const float* ad = a_d + h * D;
    float s1 = 0.f, s2 = 0.f;
    for (int d = 0; d < D; ++d) {
        float v = xr[d];
        s1 = fmaf(v, as[d], s1);
        s2 = fmaf(v, ad[d], s2);
    }
    g_ss[idx] = s1;
    g_sd[idx] = s2;
}

// ---------------- EGAT: warp/node, cp.async ef staging (padded layout), smem cWe
__global__ __launch_bounds__(256) void egat_node_kernel(
        const float* __restrict__ xv, const float* __restrict__ efc,
        const float* __restrict__ cWe, float* __restrict__ hout) {
    extern __shared__ __align__(16) float dyn[];
    float* stage = dyn;                       // EGAT_STAGE_FLOATS
    float* sWe   = dyn + EGAT_STAGE_FLOATS;   // 8192 floats

    // stage cWe (transposed, conflict-free) once per block
    for (int idx = threadIdx.x; idx < 8192; idx += 256) {
        int k = idx >> 7;
        int c = idx & 127;
        int h = c >> 4, d = c & 15;
        int kk = k & 15, kb4 = k >> 4;
        sWe[(kk * 16 + d) * 32 + kb4 * 8 + h] = cWe[idx];
    }
    __syncthreads();

    int gwarp = (blockIdx.x * blockDim.x + threadIdx.x) >> 5;   // exact fit: 6250*8 == NN
    int lane = threadIdx.x & 31;
    int wslot = (threadIdx.x >> 5);
    int n = gwarp;
    int beg = g_off[n], end = g_off[n + 1];
    int deg = end - beg;
    int G = (deg + 7) >> 3;

    int h2 = lane >> 2;
    int kb4 = lane & 3;
    int kbase = kb4 << 4;
    int lid2 = kb4 * 8 + h2;
    float sd2 = g_sd[n * 8 + h2];

    float wreg[16];
#pragma unroll
    for (int kk = 0; kk < 16; ++kk) wreg[kk] = g_wae[(kbase + kk) * 8 + h2];

    float sumex = 0.f;
    float av0 = 0.f, av1 = 0.f, av2 = 0.f, av3 = 0.f;
    float accT[16];
#pragma unroll
    for (int i = 0; i < 16; i++) accT[i] = 0.f;

    float* buf0 = stage + wslot * 2 * 8 * EGAT_ROWF;
    float* buf1 = buf0 + 8 * EGAT_ROWF;

    // cp.async dest for source 16B chunk p of edge e: e*80 + (p/4)*20 + (p%4)*4 floats
    if (G > 0) {
#pragma unroll
        for (int r = 0; r < 4; ++r) {
            int c = lane + r * 32;
            int e = c >> 4, p = c & 15;
            int i = beg + e;
            if (i < end) {
                uint32_t dst = (uint32_t)__cvta_generic_to_shared(
                    buf0 + e * EGAT_ROWF + (p >> 2) * 20 + (p & 3) * 4);
                cp16(dst, efc + (size_t)i * 64 + p * 4);
            }
        }
        asm volatile("cp.async.commit_group;");
    }

    for (int g = 0; g < G; ++g) {
        if (g + 1 < G) {
            float* nb = ((g + 1) & 1) ? buf1 : buf0;
            int nb0 = beg + (g + 1) * 8;
#pragma unroll
            for (int r = 0; r < 4; ++r) {
                int c = lane + r * 32;
                int e = c >> 4, p = c & 15;
                int i = nb0 + e;
                if (i < end) {
                    uint32_t dst = (uint32_t)__cvta_generic_to_shared(
                        nb + e * EGAT_ROWF + (p >> 2) * 20 + (p & 3) * 4);
                    cp16(dst, efc + (size_t)i * 64 + p * 4);
                }
            }
            asm volatile("cp.async.commit_group;");
            asm volatile("cp.async.wait_group 1;");
        } else {
            asm volatile("cp.async.wait_group 0;");
        }
        __syncwarp();

        float* eb = (g & 1) ? buf1 : buf0;
        int base = beg + g * 8;
        int nval = min(end - base, 8);

        int sv = (lane < nval) ? g_srcc[base + lane] : 0;
        int sj[8];
        float ssj[8];
#pragma unroll
        for (int j = 0; j < 8; ++j) sj[j] = __shfl_sync(0xffffffffu, sv, j);
#pragma unroll
        for (int j = 0; j < 8; ++j) ssj[j] = g_ss[sj[j] * 8 + h2];

        float4 xvn = *(const float4*)&xv[(size_t)sj[0] * 128 + (lane << 2)];

#pragma unroll
        for (int j = 0; j < 8; ++j) {
            if (j >= nval) break;
            float4 xvc = xvn;
            if (j + 1 < 8) xvn = *(const float4*)&xv[(size_t)sj[j + 1] * 128 + (lane << 2)];

            // lane's 16 k-values are contiguous at skewed offset kb4*20
            const float* er = eb + j * EGAT_ROWF + kb4 * 20;
            float4 e0 = *(const float4*)&er[0];
            float4 e1 = *(const float4*)&er[4];
            float4 e2 = *(const float4*)&er[8];
            float4 e3 = *(const float4*)&er[12];

            float se = e0.x * wreg[0];
            se = fmaf(e0.y, wreg[1], se);  se = fmaf(e0.z, wreg[2], se);  se = fmaf(e0.w, wreg[3], se);
            se = fmaf(e1.x, wreg[4], se);  se = fmaf(e1.y, wreg[5], se);  se = fmaf(e1.z, wreg[6], se);
            se = fmaf(e1.w, wreg[7], se);  se = fmaf(e2.x, wreg[8], se);  se = fmaf(e2.y, wreg[9], se);
            se = fmaf(e2.z, wreg[10], se); se = fmaf(e2.w, wreg[11], se); se = fmaf(e3.x, wreg[12], se);
            se = fmaf(e3.y, wreg[13], se); se = fmaf(e3.z, wreg[14], se); se = fmaf(e3.w, wreg[15], se);
            se += __shfl_xor_sync(0xffffffffu, se, 1);
            se += __shfl_xor_sync(0xffffffffu, se, 2);

            float ex = __expf(lrelu(ssj[j] + sd2 + se));
            sumex += ex;

            av0 = fmaf(ex, xvc.x, av0);
            av1 = fmaf(ex, xvc.y, av1);
            av2 = fmaf(ex, xvc.z, av2);
            av3 = fmaf(ex, xvc.w, av3);
            accT[0]  = fmaf(ex, e0.x, accT[0]);  accT[1]  = fmaf(ex, e0.y, accT[1]);
            accT[2]  = fmaf(ex, e0.z, accT[2]);  accT[3]  = fmaf(ex, e0.w, accT[3]);
            accT[4]  = fmaf(ex, e1.x, accT[4]);  accT[5]  = fmaf(ex, e1.y, accT[5]);
            accT[6]  = fmaf(ex, e1.z, accT[6]);  accT[7]  = fmaf(ex, e1.w, accT[7]);
            accT[8]  = fmaf(ex, e2.x, accT[8]);  accT[9]  = fmaf(ex, e2.y, accT[9]);
            accT[10] = fmaf(ex, e2.z, accT[10]); accT[11] = fmaf(ex, e2.w, accT[11]);
            accT[12] = fmaf(ex, e3.x, accT[12]); accT[13] = fmaf(ex, e3.y, accT[13]);
            accT[14] = fmaf(ex, e3.z, accT[14]); accT[15] = fmaf(ex, e3.w, accT[15]);
        }
        __syncwarp();
    }

    float inv = 1.f / (sumex + 1e-16f);

    float4 ov;
    ov.x = elu1(av0 * inv); ov.y = elu1(av1 * inv);
    ov.z = elu1(av2 * inv); ov.w = elu1(av3 * inv);
    *(float4*)&hout[(size_t)n * 256 + (lane << 2)] = ov;

    float pd[16];
#pragma unroll
    for (int d = 0; d < 16; ++d) pd[d] = 0.f;
#pragma unroll
    for (int kk = 0; kk < 16; ++kk) {
        float t = accT[kk];
        const float* wr = &sWe[kk * 16 * 32 + lid2];
#pragma unroll
        for (int d = 0; d < 16; ++d) pd[d] = fmaf(t, wr[d * 32], pd[d]);
    }
#pragma unroll
    for (int d = 0; d < 16; ++d) {
        pd[d] += __shfl_xor_sync(0xffffffffu, pd[d], 1);
        pd[d] += __shfl_xor_sync(0xffffffffu, pd[d], 2);
    }
    int sel = lane & 3;
    float o0, o1, o2, o3;
    if (sel == 0)      { o0 = pd[0];  o1 = pd[1];  o2 = pd[2];  o3 = pd[3]; }
    else if (sel == 1) { o0 = pd[4];  o1 = pd[5];  o2 = pd[6];  o3 = pd[7]; }
    else if (sel == 2) { o0 = pd[8];  o1 = pd[9];  o2 = pd[10]; o3 = pd[11]; }
    else               { o0 = pd[12]; o1 = pd[13]; o2 = pd[14]; o3 = pd[15]; }
    float4 on;
    on.x = elu1(o0 * inv); on.y = elu1(o1 * inv);
    on.z = elu1(o2 * inv); on.w = elu1(o3 * inv);
    *(float4*)&hout[(size_t)n * 256 + 128 + h2 * 16 + (sel << 2)] = on;
}

// ---------------- final GAT (mean over heads) with group prefetch ------------
__global__ __launch_bounds__(256) void gat_node_kernel(
        const float* __restrict__ xg, const float* __restrict__ bias,
        float* __restrict__ out) {
    int gwarp = (blockIdx.x * blockDim.x + threadIdx.x) >> 5;
    int lane = threadIdx.x & 31;
    if (gwarp >= NN) return;
    int n = gwarp;
    int beg = g_off[n], end = g_off[n + 1];
    int G = (end - beg + 7) >> 3;

    int h2 = lane >> 2;
    float sd2 = g_sd[n * 8 + h2];
    int c0 = (lane & 3) * 10;

    float acc[10];
#pragma unroll
    for (int j = 0; j < 10; j++) acc[j] = 0.f;
    float sumex = 0.f;

    for (int g = 0; g < G; ++g) {
        int base = beg + g * 8;
        int nval = min(end - base, 8);
        int sv = (lane < nval) ? g_srcc[base + lane] : 0;
        int sj[8];
        float ssj[8];
#pragma unroll
        for (int j = 0; j < 8; ++j) sj[j] = __shfl_sync(0xffffffffu, sv, j);
#pragma unroll
        for (int j = 0; j < 8; ++j) ssj[j] = g_ss[sj[j] * 8 + h2];

#pragma unroll
        for (int j = 0; j < 8; ++j) {
            if (j >= nval) break;
            float ex = __expf(lrelu(ssj[j] + sd2));
            sumex += ex;
            const float* xr = &xg[(size_t)sj[j] * 320 + h2 * 40 + c0];
#pragma unroll
            for (int q = 0; q < 10; q += 2) {
                float2 t = *(const float2*)&xr[q];
                acc[q]     = fmaf(ex, t.x, acc[q]);
                acc[q + 1] = fmaf(ex, t.y, acc[q + 1]);
            }
        }
    }
    float inv = 1.f / (sumex + 1e-16f);
#pragma unroll
    for (int j = 0; j < 10; ++j) {
        float v = acc[j] * inv;
        v += __shfl_xor_sync(0xffffffffu, v, 4);
        v += __shfl_xor_sync(0xffffffffu, v, 8);
        v += __shfl_xor_sync(0xffffffffu, v, 16);
        acc[j] = v;
    }
    if (lane < 4) {
#pragma unroll
        for (int j = 0; j < 10; ++j)
            out[(size_t)n * 40 + lane * 10 + j] = acc[j] * 0.125f + bias[lane * 10 + j];
    }
}

// ---------------- host ----------------
static inline dim3 ggrid(int M, int Cn) { return dim3((unsigned)((M + 127) / 128), (unsigned)(Cn / 64)); }

extern "C" void kernel_launch(void* const* d_in, const int* in_sizes, int n_in,
                              void* d_out, int out_size) {
    (void)in_sizes; (void)n_in; (void)out_size;
    const float* x     = (const float*)d_in[0];
    const int*   ei32  = (const int*)d_in[1];
    const float* ea    = (const float*)d_in[2];
    const float* e1_Ws = (const float*)d_in[3];
    const float* e1_Wd = (const float*)d_in[4];
    const float* e1_We = (const float*)d_in[5];
    const float* e1_b  = (const float*)d_in[6];
    const float* c1_Wv = (const float*)d_in[7];
    const float* c1_We = (const float*)d_in[8];
    const float* c1_as = (const float*)d_in[9];
    const float* c1_ad = (const float*)d_in[10];
    const float* c1_ae = (const float*)d_in[11];
    const float* e2_Ws = (const float*)d_in[12];
    const float* e2_Wd = (const float*)d_in[13];
    const float* e2_We = (const float*)d_in[14];
    const float* e2_b  = (const float*)d_in[15];
    const float* c2_Wv = (const float*)d_in[16];
    const float* c2_We = (const float*)d_in[17];
    const float* c2_as = (const float*)d_in[18];
    const float* c2_ad = (const float*)d_in[19];
    const float* c2_ae = (const float*)d_in[20];
    const float* g_Wp  = (const float*)d_in[21];
    const float* g_asP = (const float*)d_in[22];
    const float* g_adP = (const float*)d_in[23];
    const float* g_bP  = (const float*)d_in[24];
    float* out = (float*)d_out;

    void *p_efA, *p_efB, *p_xv, *p_h1, *p_h2, *p_xg;
    cudaGetSymbolAddress(&p_efA, g_efA);
    cudaGetSymbolAddress(&p_efB, g_efB);
    cudaGetSymbolAddress(&p_xv,  g_xv);
    cudaGetSymbolAddress(&p_h1,  g_h1);
    cudaGetSymbolAddress(&p_h2,  g_h2);
    cudaGetSymbolAddress(&p_xg,  g_xg);
    float* efA = (float*)p_efA; float* efB = (float*)p_efB;
    float* xv  = (float*)p_xv;  float* h1  = (float*)p_h1;
    float* h2  = (float*)p_h2;  float* xg  = (float*)p_xg;

    cudaFuncSetAttribute(egat_node_kernel,
                         cudaFuncAttributeMaxDynamicSharedMemorySize, EGAT_SMEM_BYTES);

    int nsgrid = (NN * 8 + 255) / 256 + 1;

    prep_kernel<<<(EE + 255) / 256, 256>>>(ei32);                               // 1
    count_kernel<<<(EE + 255) / 256, 256>>>();                                  // 2
    scan_kernel<<<1, 1024>>>();                                                 // 3
    gemm3_kernel<<<dim3((NN + 127) / 128, 4), 256>>>(x, e1_Ws, e1_Wd, c1_Wv, NN, 128); // 4 <- ncu
    scatter_kernel<<<(EE + 255) / 256, 256>>>();                                // 5
    gemm_kernel<<<ggrid(EE, 64), 256>>>(ea, e1_We, efA, EE, 16, 64, 1, e1_b);   // 6
    node_scalar_kernel<<<nsgrid, 256>>>(xv, c1_as, c1_ad, 16, c1_We, c1_ae);    // 7
    egat_node_kernel<<<(NN + 7) / 8, 256, EGAT_SMEM_BYTES>>>(xv, efA, c1_We, h1); // 8

    gemm3_kernel<<<dim3((NN + 127) / 128, 4), 256>>>(h1, e2_Ws, e2_Wd, c2_Wv, NN, 256); // 9
    gemm_kernel<<<ggrid(EE, 64), 256>>>(efA, e2_We, efB, EE, 64, 64, 2, e2_b);  // 10
    node_scalar_kernel<<<nsgrid, 256>>>(xv, c2_as, c2_ad, 16, c2_We, c2_ae);    // 11
    egat_node_kernel<<<(NN + 7) / 8, 256, EGAT_SMEM_BYTES>>>(xv, efB, c2_We, h2); // 12

    gemm_kernel<<<ggrid(NN, 320), 256>>>(h2, g_Wp, xg, NN, 256, 320, 0, nullptr); // 13
    node_scalar_kernel<<<nsgrid - 1, 256>>>(xg, g_asP, g_adP, 40, nullptr, nullptr); // 14
    gat_node_kernel<<<(NN + 7) / 8, 256>>>(xg, g_bP, out);                      // 15
}